// round 12
// baseline (speedup 1.0000x reference)
#include <cuda_runtime.h>
#include <cuda_fp16.h>
#include <cstdint>

#define NTOT 16384
#define BLB  4096
#define BULB 6144
#define DIM  128
#define NC   10
#define LSTB 24
#define NSLOT 66

// ---------------- device scratch ----------------
__device__ __align__(256) __half g_F[NTOT * DIM];
__device__ __align__(256) __half g_Lh[NTOT * LSTB];     // 10 probs, [10]=1, rest 0
__device__ __align__(256) float g_part[128 * NSLOT * 128 * 12];  // 52 MB partials
__device__ float g_cnt[NC];

// ---------------- helpers ----------------
__device__ __forceinline__ float ex2a(float x) {
    float y; asm("ex2.approx.ftz.f32 %0,%1;" : "=f"(y) : "f"(x)); return y;
}
__device__ __forceinline__ void cpa16(uint32_t dst, const void* src) {
    asm volatile("cp.async.cg.shared.global [%0], [%1], 16;" :: "r"(dst), "l"(src));
}
#define CPC()  asm volatile("cp.async.commit_group;" ::: "memory")
#define CPW(n) asm volatile("cp.async.wait_group %0;" :: "n"(n) : "memory")

__device__ __forceinline__ void ldsm4(uint32_t* r, uint32_t a) {
    asm volatile("ldmatrix.sync.aligned.m8n8.x4.shared.b16 {%0,%1,%2,%3},[%4];"
        : "=r"(r[0]), "=r"(r[1]), "=r"(r[2]), "=r"(r[3]) : "r"(a));
}
__device__ __forceinline__ void ldsm4t(uint32_t* r, uint32_t a) {
    asm volatile("ldmatrix.sync.aligned.m8n8.x4.trans.shared.b16 {%0,%1,%2,%3},[%4];"
        : "=r"(r[0]), "=r"(r[1]), "=r"(r[2]), "=r"(r[3]) : "r"(a));
}
__device__ __forceinline__ void mmaf16(float* d, const uint32_t* a, uint32_t b0, uint32_t b1) {
    asm volatile("mma.sync.aligned.m16n8k16.row.col.f32.f16.f16.f32 "
        "{%0,%1,%2,%3},{%4,%5,%6,%7},{%8,%9},{%0,%1,%2,%3};"
        : "+f"(d[0]), "+f"(d[1]), "+f"(d[2]), "+f"(d[3])
        : "r"(a[0]), "r"(a[1]), "r"(a[2]), "r"(a[3]), "r"(b0), "r"(b1));
}
__device__ __forceinline__ uint32_t packh(float lo, float hi) {
    uint32_t r; asm("cvt.rn.f16x2.f32 %0, %1, %2;" : "=r"(r) : "f"(hi), "f"(lo)); return r;
}
__device__ __forceinline__ void sts32(uint32_t a, uint32_t v) {
    asm volatile("st.shared.b32 [%0],%1;" :: "r"(a), "r"(v) : "memory");
}

// ---------------- smem layout (byte offsets from 1024-aligned base) ----------------
#define S_Q     0
#define S_K(b)  (32768 + (b) * 32768)      // 3 buffers
#define S_W(b)  (131072 + (b) * 32768)     // 2 buffers
#define S_L(b)  (196608 + (b) * 6144)      // 3 buffers
#define SMEM_REQ (215040 + 1024)

// SW128 blocked layout for a 128x128 fp16 tile (row 0..127, 16B-chunk 0..15)
__device__ __forceinline__ uint32_t swoff(int row, int ch) {
    return (uint32_t)(((row >> 3) * 1024) + ((ch >> 3) * 16384)
                      + ((row & 7) * 128) + ((((ch & 7) ^ (row & 7)) << 4)));
}

__device__ __forceinline__ void load_ftile(uint32_t dst, int rowbase, int tid) {
#pragma unroll
    for (int i = 0; i < 4; i++) {
        int idx = i * 512 + tid;
        int row = idx >> 4, ch = idx & 15;
        cpa16(dst + swoff(row, ch), g_F + (size_t)(rowbase + row) * DIM + ch * 8);
    }
}
__device__ __forceinline__ void load_ltile(uint32_t dst, int rowbase, int tid) {
    if (tid < 384) {
        int row = tid / 3, part = tid - row * 3;
        cpa16(dst + (uint32_t)(row * 48 + part * 16),
              g_Lh + (size_t)(rowbase + row) * LSTB + part * 8);
    }
}

// ---------------- prep kernels ----------------
__global__ void k_zero() { if (threadIdx.x < NC) g_cnt[threadIdx.x] = 0.f; }

__global__ void k_prep_lb(const float* __restrict__ oh) {
    int r = blockIdx.x * blockDim.x + threadIdx.x;
    if (r >= BLB) return;
#pragma unroll
    for (int c = 0; c < NC; c++) {
        float v = oh[r * NC + c];
        g_Lh[r * LSTB + c] = __float2half(v);
        if (v != 0.f) atomicAdd(&g_cnt[c], v);
    }
    g_Lh[r * LSTB + 10] = __float2half(1.0f);
#pragma unroll
    for (int c = 11; c < LSTB; c++) g_Lh[r * LSTB + c] = __float2half(0.0f);
}

__global__ void k_prep_ulb(const float* __restrict__ l1, const float* __restrict__ l2) {
    int r = blockIdx.x * blockDim.x + threadIdx.x;
    if (r >= BULB) return;
    float a[NC], b[NC];
#pragma unroll
    for (int i = 0; i < NC; i++) { a[i] = l1[r*NC+i]; b[i] = l2[r*NC+i]; }
    float m1 = -1e30f, m2 = -1e30f;
#pragma unroll
    for (int i = 0; i < NC; i++) { m1 = fmaxf(m1, a[i]); m2 = fmaxf(m2, b[i]); }
    float s1 = 0.f, s2 = 0.f;
#pragma unroll
    for (int i = 0; i < NC; i++) { s1 += expf(2.f*(a[i]-m1)); s2 += expf(2.f*(b[i]-m2)); }
    bool take1 = (s1 <= s2);
    float lg[NC];
#pragma unroll
    for (int i = 0; i < NC; i++) lg[i] = take1 ? a[i] : b[i];

    float m = -1e30f;
#pragma unroll
    for (int i = 0; i < NC; i++) m = fmaxf(m, lg[i]);
    float e[NC], s = 0.f;
#pragma unroll
    for (int i = 0; i < NC; i++) { e[i] = expf(lg[i]-m); s += e[i]; }
#pragma unroll
    for (int i = 0; i < NC; i++) if (e[i] < 0.95f * s) lg[i] = 0.f;

    float mx = lg[0]; int idx = 0;
#pragma unroll
    for (int i = 1; i < NC; i++) if (lg[i] > mx) { mx = lg[i]; idx = i; }
    if (mx != 0.f) atomicAdd(&g_cnt[idx], 2.f);

    float mm = -1e30f;
#pragma unroll
    for (int i = 0; i < NC; i++) mm = fmaxf(mm, lg[i]);
    float p[NC], ss = 0.f;
#pragma unroll
    for (int i = 0; i < NC; i++) { p[i] = expf(2.f*(lg[i]-mm)); ss += p[i]; }
    float inv = 1.f / ss;
    int r1 = BLB + r, r2 = BLB + BULB + r;
#pragma unroll
    for (int c = 0; c < NC; c++) {
        __half v = __float2half(p[c] * inv);
        g_Lh[r1*LSTB + c] = v; g_Lh[r2*LSTB + c] = v;
    }
    g_Lh[r1*LSTB + 10] = __float2half(1.0f);
    g_Lh[r2*LSTB + 10] = __float2half(1.0f);
#pragma unroll
    for (int c = 11; c < LSTB; c++) {
        g_Lh[r1*LSTB + c] = __float2half(0.0f);
        g_Lh[r2*LSTB + c] = __float2half(0.0f);
    }
}

__global__ void k_norm(const float* __restrict__ lb, const float* __restrict__ an,
                       const float* __restrict__ po) {
    int w = (blockIdx.x * blockDim.x + threadIdx.x) >> 5;
    int ln = threadIdx.x & 31;
    if (w >= NTOT) return;
    const float* s = (w < BLB) ? lb + (size_t)w * DIM
                   : (w < BLB + BULB) ? an + (size_t)(w - BLB) * DIM
                                      : po + (size_t)(w - BLB - BULB) * DIM;
    float4 v = ((const float4*)s)[ln];
    float q = v.x*v.x + v.y*v.y + v.z*v.z + v.w*v.w;
#pragma unroll
    for (int o = 16; o; o >>= 1) q += __shfl_xor_sync(0xffffffffu, q, o);
    float iv = 1.f / fmaxf(sqrtf(q), 1e-12f);
    __half2 h0 = __floats2half2_rn(v.x * iv, v.y * iv);
    __half2 h1 = __floats2half2_rn(v.z * iv, v.w * iv);
    size_t base = (size_t)w * DIM + ln * 4;
    *(__half2*)(g_F + base)     = h0;
    *(__half2*)(g_F + base + 2) = h1;
}

// ---------------- main attention kernel: symmetric tiles, 512 threads ----------------
// CTA c computes tiles (c, (c+d)&127) for d=0..NT-1.
// Warp w: band = w&7 (16 q-rows), qh = w>>3 (n-half for QK/local PV; col-half for trans PV).
__global__ void __launch_bounds__(512, 1) k_attn() {
    extern __shared__ char smraw[];
    uint32_t sb0;
    asm("{\n.reg .u64 t;\ncvta.to.shared.u64 t, %1;\ncvt.u32.u64 %0, t;\n}" : "=r"(sb0) : "l"(smraw));
    uint32_t sb = (sb0 + 1023u) & ~1023u;

    int tid = threadIdx.x, wid = tid >> 5, lane = tid & 31;
    int band = wid & 7, qh = wid >> 3;
    int c = blockIdx.x;
    int lr = lane & 7, lg = lane >> 3;
    int hbit = lg >> 1;
    int rbit = lg & 1;
    int NT = (c < 64) ? 65 : 64;

    // prologue: group0 = {Q, K0, L0}; group1 = {K1, L1}
    load_ftile(sb + S_Q, c * 128, tid);
    load_ftile(sb + S_K(0), c * 128, tid);
    load_ltile(sb + S_L(0), c * 128, tid);
    CPC();
    {
        int j1 = (c + 1) & 127;
        load_ftile(sb + S_K(1), j1 * 128, tid);
        load_ltile(sb + S_L(1), j1 * 128, tid);
        CPC();
    }
    CPW(1);              // group0 complete
    __syncthreads();

    // per-lane ldmatrix address components
    int row_a = 16 * band + rbit * 8 + lr;
    uint32_t aR = (uint32_t)(((row_a >> 3) * 1024) + ((row_a & 7) * 128));
    uint32_t ax = (uint32_t)(row_a & 7);
    int r0 = rbit * 8 + lr;
    uint32_t bR = (uint32_t)(((r0 >> 3) * 1024) + ((r0 & 7) * 128));
    uint32_t bx = (uint32_t)(r0 & 7);
    uint32_t lOff = (uint32_t)((hbit * 8 + lr) * 48 + rbit * 16);

    uint32_t A[8][4];
#pragma unroll
    for (int s = 0; s < 8; s++) {
        int ch = 2 * s + hbit;
        uint32_t cA = (uint32_t)(((ch >> 3) * 16384) + ((((uint32_t)(ch & 7) ^ ax) << 4)));
        ldsm4(A[s], sb + S_Q + aR + cA);
    }
    uint32_t cB[8];
#pragma unroll
    for (int s = 0; s < 8; s++) {
        int ch = 2 * s + hbit;
        cB[s] = (uint32_t)(((ch >> 3) * 16384) + ((((uint32_t)(ch & 7) ^ bx) << 4)));
    }
    // L_c B-fragments for transposed PV: keep only this warp's column-half
    uint32_t LCa[8], LCb[8];
#pragma unroll
    for (int s = 0; s < 8; s++) {
        uint32_t tmp[4];
        ldsm4t(tmp, sb + S_L(0) + lOff + (uint32_t)(s * 768));
        LCa[s] = qh ? tmp[1] : tmp[0];
        LCb[s] = qh ? tmp[3] : tmp[2];
    }

    // W-store / W^T-load address components
    int rW = 16 * band + (lane >> 2);
    uint32_t wIn = (uint32_t)(4 * (lane & 3));
    int qbase = ((lane >> 4) << 3) + (lane & 7);
    int chW = 2 * band + ((lane >> 3) & 1);

    float O0[4] = {0.f, 0.f, 0.f, 0.f};
    float O1[4] = {0.f, 0.f, 0.f, 0.f};
    const float C = 2.8853900817779268f;   // 2/ln2

    for (int d = 0; d < NT; d++) {
        int kb = d % 3;
        int wb = d & 1;
        int j = (c + d) & 127;
        if (d + 2 < NT) {
            int jn = (c + d + 2) & 127;
            load_ftile(sb + S_K((d + 2) % 3), jn * 128, tid);
            load_ltile(sb + S_L((d + 2) % 3), jn * 128, tid);
            CPC();
            CPW(2);      // group d complete; d+1, d+2 in flight
        } else if (d + 1 < NT) {
            CPW(1);      // group d complete; d+1 in flight
        } else {
            CPW(0);
        }
        uint32_t KH = sb + S_K(kb) + bR;
        uint32_t Lb = sb + (uint32_t)S_L(kb) + lOff;
        uint32_t WB = sb + (uint32_t)S_W(wb);

        // QK + exp + local PV + W store, for this warp's 4 n-tiles
#pragma unroll
        for (int pp = 0; pp < 4; pp++) {
            int p = 4 * qh + pp;
            float S0[4] = {0.f, 0.f, 0.f, 0.f};
            float S1[4] = {0.f, 0.f, 0.f, 0.f};
            uint32_t kbad = KH + (uint32_t)(p * 2048);
#pragma unroll
            for (int s = 0; s < 8; s++) {
                uint32_t bb[4];
                ldsm4(bb, kbad + cB[s]);
                mmaf16(S0, A[s], bb[0], bb[2]);
                mmaf16(S1, A[s], bb[1], bb[3]);
            }
            uint32_t W[4];
            W[0] = packh(ex2a(S0[0] * C), ex2a(S0[1] * C));
            W[1] = packh(ex2a(S0[2] * C), ex2a(S0[3] * C));
            W[2] = packh(ex2a(S1[0] * C), ex2a(S1[1] * C));
            W[3] = packh(ex2a(S1[2] * C), ex2a(S1[3] * C));
            // local PV (n-partial; full 16 output cols)
            uint32_t bf[4];
            ldsm4t(bf, Lb + (uint32_t)(p * 768));
            mmaf16(O0, W, bf[0], bf[2]);
            mmaf16(O1, W, bf[1], bf[3]);
            // store W for the transpose pass
            sts32(WB + swoff(rW, 2 * p) + wIn,         W[0]);
            sts32(WB + swoff(rW + 8, 2 * p) + wIn,     W[1]);
            sts32(WB + swoff(rW, 2 * p + 1) + wIn,     W[2]);
            sts32(WB + swoff(rW + 8, 2 * p + 1) + wIn, W[3]);
        }

        __syncthreads();   // W(d) complete; K(d)/L(d) reads done

        if (d > 0) {
            // transposed PV: krows 16*band, output column-half qh, full q contraction
            float F[4] = {0.f, 0.f, 0.f, 0.f};
#pragma unroll
            for (int s = 0; s < 8; s++) {
                uint32_t At[4];
                ldsm4t(At, WB + swoff(16 * s + qbase, chW));
                mmaf16(F, At, LCa[s], LCb[s]);
            }
            int slot = (d < 64) ? (d - 1) : 63;
            int krow = 16 * band + (lane >> 2);
            int cp = 2 * (lane & 3);
            float* pb = g_part + (((size_t)j * NSLOT + slot) * 128 + krow) * 12;
            if (qh == 0) {
                *(float2*)(pb + cp)          = make_float2(F[0], F[1]);
                *(float2*)(pb + 8 * 12 + cp) = make_float2(F[2], F[3]);
            } else if ((lane & 3) < 2) {
                *(float2*)(pb + 8 + cp)          = make_float2(F[0], F[1]);
                *(float2*)(pb + 8 * 12 + 8 + cp) = make_float2(F[2], F[3]);
            }
        }
    }

    // local n-partial -> slot 64+qh of row-block c
    {
        int qrow = 16 * band + (lane >> 2);
        int cp = 2 * (lane & 3);
        float* pb = g_part + (((size_t)c * NSLOT + 64 + qh) * 128 + qrow) * 12;
        *(float2*)(pb + cp)          = make_float2(O0[0], O0[1]);
        *(float2*)(pb + 8 * 12 + cp) = make_float2(O0[2], O0[3]);
        if ((lane & 3) < 2) {
            *(float2*)(pb + 8 + cp)          = make_float2(O1[0], O1[1]);
            *(float2*)(pb + 8 * 12 + 8 + cp) = make_float2(O1[2], O1[3]);
        }
    }
}

// ---------------- reduction kernel ----------------
__global__ void __launch_bounds__(256) k_red(float* __restrict__ out) {
    __shared__ float acc[1536];
    __shared__ float sInv[NC];
    int j = blockIdx.x, tid = threadIdx.x;
    if (tid == 0) {
        float tot = 0.f;
#pragma unroll
        for (int q = 0; q < NC; q++) tot += g_cnt[q];
#pragma unroll
        for (int q = 0; q < NC; q++) {
            float dd = g_cnt[q];
            sInv[q] = 1.f / ((dd == 0.f) ? tot : dd);
        }
    }
    int nfore = (j >= 64) ? 64 : 63;   // slots 0..62 (+63 if j>=64)
    const float* base = g_part + (size_t)j * NSLOT * 1536;
#pragma unroll
    for (int i = 0; i < 6; i++) {
        int e = i * 256 + tid;
        float s = base[(size_t)64 * 1536 + e] + base[(size_t)65 * 1536 + e];  // local halves
        int sl = 0;
        for (; sl + 4 <= nfore; sl += 4) {
            s += base[(size_t)sl * 1536 + e] + base[(size_t)(sl+1) * 1536 + e]
               + base[(size_t)(sl+2) * 1536 + e] + base[(size_t)(sl+3) * 1536 + e];
        }
        for (; sl < nfore; sl++) s += base[(size_t)sl * 1536 + e];
        acc[e] = s;
    }
    __syncthreads();
    for (int t = tid; t < 128 * NC; t += 256) {
        int row = t / NC, q = t - row * NC;
        out[((size_t)j * 128 + row) * NC + q] = acc[row * 12 + q] / acc[row * 12 + 10] * sInv[q];
    }
}

// ---------------- launcher ----------------
extern "C" void kernel_launch(void* const* d_in, const int* in_sizes, int n_in,
                              void* d_out, int out_size) {
    const float* anchor   = (const float*)d_in[0];
    const float* positive = (const float*)d_in[1];
    const float* lb_feat  = (const float*)d_in[2];
    const float* lb_oh    = (const float*)d_in[3];
    const float* logits1  = (const float*)d_in[4];
    const float* logits2  = (const float*)d_in[5];
    float* out = (float*)d_out;

    cudaFuncSetAttribute(k_attn, cudaFuncAttributeMaxDynamicSharedMemorySize, SMEM_REQ);

    k_zero<<<1, 32>>>();
    k_prep_lb<<<BLB / 256, 256>>>(lb_oh);
    k_prep_ulb<<<BULB / 256, 256>>>(logits1, logits2);
    k_norm<<<(NTOT * 32) / 256, 256>>>(lb_feat, anchor, positive);
    k_attn<<<128, 512, SMEM_REQ>>>();
    k_red<<<128, 256>>>(out);
}

// round 13
// speedup vs baseline: 1.2731x; 1.2731x over previous
#include <cuda_runtime.h>
#include <cuda_fp16.h>
#include <cstdint>

#define NTOT 16384
#define BLB  4096
#define BULB 6144
#define DIM  128
#define NC   10
#define LSTB 24
#define NSLOT 67
#define TTOT 8256   // 64*65 + 64*64 symmetric tiles

// ---------------- device scratch ----------------
__device__ __align__(256) __half g_F[NTOT * DIM];
__device__ __align__(256) __half g_Lh[NTOT * LSTB];     // 10 probs, [10]=1, rest 0
__device__ __align__(256) float g_part[128 * NSLOT * 128 * 12];  // ~53 MB partials
__device__ float g_cnt[NC];

// ---------------- helpers ----------------
__device__ __forceinline__ float ex2a(float x) {
    float y; asm("ex2.approx.ftz.f32 %0,%1;" : "=f"(y) : "f"(x)); return y;
}
__device__ __forceinline__ void cpa16(uint32_t dst, const void* src) {
    asm volatile("cp.async.cg.shared.global [%0], [%1], 16;" :: "r"(dst), "l"(src));
}
#define CPC()  asm volatile("cp.async.commit_group;" ::: "memory")
#define CPW(n) asm volatile("cp.async.wait_group %0;" :: "n"(n) : "memory")

__device__ __forceinline__ void ldsm4(uint32_t* r, uint32_t a) {
    asm volatile("ldmatrix.sync.aligned.m8n8.x4.shared.b16 {%0,%1,%2,%3},[%4];"
        : "=r"(r[0]), "=r"(r[1]), "=r"(r[2]), "=r"(r[3]) : "r"(a));
}
__device__ __forceinline__ void ldsm4t(uint32_t* r, uint32_t a) {
    asm volatile("ldmatrix.sync.aligned.m8n8.x4.trans.shared.b16 {%0,%1,%2,%3},[%4];"
        : "=r"(r[0]), "=r"(r[1]), "=r"(r[2]), "=r"(r[3]) : "r"(a));
}
__device__ __forceinline__ void mmaf16(float* d, const uint32_t* a, uint32_t b0, uint32_t b1) {
    asm volatile("mma.sync.aligned.m16n8k16.row.col.f32.f16.f16.f32 "
        "{%0,%1,%2,%3},{%4,%5,%6,%7},{%8,%9},{%0,%1,%2,%3};"
        : "+f"(d[0]), "+f"(d[1]), "+f"(d[2]), "+f"(d[3])
        : "r"(a[0]), "r"(a[1]), "r"(a[2]), "r"(a[3]), "r"(b0), "r"(b1));
}
__device__ __forceinline__ uint32_t packh(float lo, float hi) {
    uint32_t r; asm("cvt.rn.f16x2.f32 %0, %1, %2;" : "=r"(r) : "f"(hi), "f"(lo)); return r;
}
__device__ __forceinline__ void sts32(uint32_t a, uint32_t v) {
    asm volatile("st.shared.b32 [%0],%1;" :: "r"(a), "r"(v) : "memory");
}
__device__ __forceinline__ float4 f4add(float4 a, float4 b) {
    return make_float4(a.x + b.x, a.y + b.y, a.z + b.z, a.w + b.w);
}

// ---------------- smem layout (byte offsets from 1024-aligned base) ----------------
#define S_Q     0
#define S_K(b)  (32768 + (b) * 32768)      // 3 buffers
#define S_W(b)  (131072 + (b) * 32768)     // 2 buffers
#define S_L(b)  (196608 + (b) * 6144)      // 3 buffers
#define S_LC    215040                     // L_c copy for trans PV
#define SMEM_REQ (221184 + 1024)

// SW128 blocked layout for a 128x128 fp16 tile (row 0..127, 16B-chunk 0..15)
__device__ __forceinline__ uint32_t swoff(int row, int ch) {
    return (uint32_t)(((row >> 3) * 1024) + ((ch >> 3) * 16384)
                      + ((row & 7) * 128) + ((((ch & 7) ^ (row & 7)) << 4)));
}

__device__ __forceinline__ void load_ftile(uint32_t dst, int rowbase, int tid) {
#pragma unroll
    for (int i = 0; i < 8; i++) {
        int idx = i * 256 + tid;
        int row = idx >> 4, ch = idx & 15;
        cpa16(dst + swoff(row, ch), g_F + (size_t)(rowbase + row) * DIM + ch * 8);
    }
}
__device__ __forceinline__ void load_ltile(uint32_t dst, int rowbase, int tid) {
#pragma unroll
    for (int i = 0; i < 2; i++) {
        int idx = i * 256 + tid;
        if (idx < 384) {
            int row = idx / 3, part = idx - row * 3;
            cpa16(dst + (uint32_t)(row * 48 + part * 16),
                  g_Lh + (size_t)(rowbase + row) * LSTB + part * 8);
        }
    }
}

// ---------------- prep: normalize + zero counters/slots ----------------
__global__ void k_norm(const float* __restrict__ lb, const float* __restrict__ an,
                       const float* __restrict__ po) {
    int gt = blockIdx.x * blockDim.x + threadIdx.x;
    if (gt < NC) g_cnt[gt] = 0.f;
    if (gt < 128 * 2 * 1536) {            // zero helper local slots 65,66
        int j = gt / 3072, r = gt - j * 3072;
        g_part[((size_t)j * NSLOT + 65) * 1536 + r] = 0.f;
    }
    int w = gt >> 5;
    int ln = threadIdx.x & 31;
    if (w >= NTOT) return;
    const float* s = (w < BLB) ? lb + (size_t)w * DIM
                   : (w < BLB + BULB) ? an + (size_t)(w - BLB) * DIM
                                      : po + (size_t)(w - BLB - BULB) * DIM;
    float4 v = ((const float4*)s)[ln];
    float q = v.x*v.x + v.y*v.y + v.z*v.z + v.w*v.w;
#pragma unroll
    for (int o = 16; o; o >>= 1) q += __shfl_xor_sync(0xffffffffu, q, o);
    float iv = 1.f / fmaxf(sqrtf(q), 1e-12f);
    __half2 h0 = __floats2half2_rn(v.x * iv, v.y * iv);
    __half2 h1 = __floats2half2_rn(v.z * iv, v.w * iv);
    size_t base = (size_t)w * DIM + ln * 4;
    *(__half2*)(g_F + base)     = h0;
    *(__half2*)(g_F + base + 2) = h1;
}

// ---------------- prep: labeled + unlabeled logits (fused) ----------------
__global__ void __launch_bounds__(256) k_prep(const float* __restrict__ oh,
                                              const float* __restrict__ l1,
                                              const float* __restrict__ l2) {
    int bid = blockIdx.x, tid = threadIdx.x;
    if (bid < 16) {
        int r = bid * 256 + tid;
#pragma unroll
        for (int c = 0; c < NC; c++) {
            float v = oh[r * NC + c];
            g_Lh[r * LSTB + c] = __float2half(v);
            if (v != 0.f) atomicAdd(&g_cnt[c], v);
        }
        g_Lh[r * LSTB + 10] = __float2half(1.0f);
#pragma unroll
        for (int c = 11; c < LSTB; c++) g_Lh[r * LSTB + c] = __float2half(0.0f);
        return;
    }
    int r = (bid - 16) * 256 + tid;
    float a[NC], b[NC];
#pragma unroll
    for (int i = 0; i < NC; i++) { a[i] = l1[r*NC+i]; b[i] = l2[r*NC+i]; }
    float m1 = -1e30f, m2 = -1e30f;
#pragma unroll
    for (int i = 0; i < NC; i++) { m1 = fmaxf(m1, a[i]); m2 = fmaxf(m2, b[i]); }
    float s1 = 0.f, s2 = 0.f;
#pragma unroll
    for (int i = 0; i < NC; i++) { s1 += expf(2.f*(a[i]-m1)); s2 += expf(2.f*(b[i]-m2)); }
    bool take1 = (s1 <= s2);
    float lg[NC];
#pragma unroll
    for (int i = 0; i < NC; i++) lg[i] = take1 ? a[i] : b[i];

    float m = -1e30f;
#pragma unroll
    for (int i = 0; i < NC; i++) m = fmaxf(m, lg[i]);
    float e[NC], s = 0.f;
#pragma unroll
    for (int i = 0; i < NC; i++) { e[i] = expf(lg[i]-m); s += e[i]; }
#pragma unroll
    for (int i = 0; i < NC; i++) if (e[i] < 0.95f * s) lg[i] = 0.f;

    float mx = lg[0]; int idx = 0;
#pragma unroll
    for (int i = 1; i < NC; i++) if (lg[i] > mx) { mx = lg[i]; idx = i; }
    if (mx != 0.f) atomicAdd(&g_cnt[idx], 2.f);

    float mm = -1e30f;
#pragma unroll
    for (int i = 0; i < NC; i++) mm = fmaxf(mm, lg[i]);
    float p[NC], ss = 0.f;
#pragma unroll
    for (int i = 0; i < NC; i++) { p[i] = expf(2.f*(lg[i]-mm)); ss += p[i]; }
    float inv = 1.f / ss;
    int r1 = BLB + r, r2 = BLB + BULB + r;
#pragma unroll
    for (int c = 0; c < NC; c++) {
        __half v = __float2half(p[c] * inv);
        g_Lh[r1*LSTB + c] = v; g_Lh[r2*LSTB + c] = v;
    }
    g_Lh[r1*LSTB + 10] = __float2half(1.0f);
    g_Lh[r2*LSTB + 10] = __float2half(1.0f);
#pragma unroll
    for (int c = 11; c < LSTB; c++) {
        g_Lh[r1*LSTB + c] = __float2half(0.0f);
        g_Lh[r2*LSTB + c] = __float2half(0.0f);
    }
}

// ---------------- main attention: symmetric tiles, 128 mains + H helpers ----------------
// Main CTA c: tiles (c, c+d) d=0..m-1, local slot 64.
// Helper CTAs split the c-major tail list (d=m..64 for c<64, m..63 for c>=64)
// into contiguous runs; run local partial -> slot 65 (run starts at d=m) or 66.
__global__ void __launch_bounds__(256, 1) k_attn(int m) {
    extern __shared__ char smraw[];
    uint32_t sb0;
    asm("{\n.reg .u64 t;\ncvta.to.shared.u64 t, %1;\ncvt.u32.u64 %0, t;\n}" : "=r"(sb0) : "l"(smraw));
    uint32_t sb = (sb0 + 1023u) & ~1023u;

    int tid = threadIdx.x, wid = tid >> 5, lane = tid & 31;
    int lr = lane & 7, lg = lane >> 3;
    int hbit = lg >> 1;
    int rbit = lg & 1;
    int bid = blockIdx.x;
    int H = (int)gridDim.x - 128;

    // lane-constant address components (c-independent)
    int row_a = 16 * wid + rbit * 8 + lr;
    uint32_t aR = (uint32_t)(((row_a >> 3) * 1024) + ((row_a & 7) * 128));
    uint32_t ax = (uint32_t)(row_a & 7);
    int r0 = rbit * 8 + lr;
    uint32_t bR = (uint32_t)(((r0 >> 3) * 1024) + ((r0 & 7) * 128));
    uint32_t bx = (uint32_t)(r0 & 7);
    uint32_t lOff = (uint32_t)((hbit * 8 + lr) * 48 + rbit * 16);
    uint32_t cB[8];
#pragma unroll
    for (int s = 0; s < 8; s++) {
        int ch = 2 * s + hbit;
        cB[s] = (uint32_t)(((ch >> 3) * 16384) + ((((uint32_t)(ch & 7) ^ bx) << 4)));
    }
    int rW = 16 * wid + (lane >> 2);
    uint32_t wIn = (uint32_t)(4 * (lane & 3));
    int qbase = ((lane >> 4) << 3) + (lane & 7);
    int chW = 2 * wid + ((lane >> 3) & 1);
    const float C = 2.8853900817779268f;   // 2/ln2

    int A1 = 65 - m, A2 = 64 - m, tail = TTOT - 128 * m;
    int t = 0, tend = 0;
    if (bid >= 128) {
        int q = (tail + H - 1) / H;
        t = (bid - 128) * q;
        tend = min(tail, t + q);
        if (t >= tend) return;
    }

    for (;;) {   // segment loop
        int c, d0, len, lslot;
        if (bid < 128) {
            c = bid; d0 = 0; lslot = 64;
            len = (H > 0) ? m : ((c < 64) ? 65 : 64);
        } else {
            int b1 = 64 * A1;
            if (t < b1) { c = t / A1; int o = t - c * A1; d0 = m + o; len = A1 - o; }
            else { int u = t - b1; int cc = u / A2; c = 64 + cc; int o = u - cc * A2; d0 = m + o; len = A2 - o; }
            if (len > tend - t) len = tend - t;
            lslot = (d0 == m) ? 65 : 66;
        }

        // segment prologue: G0={Q,LC}, G1={K(d0),L(d0)}, G2={K(d0+1),L(d0+1)}
        load_ftile(sb + S_Q, c * 128, tid);
        load_ltile(sb + S_LC, c * 128, tid);
        CPC();
        load_ftile(sb + S_K(0), ((c + d0) & 127) * 128, tid);
        load_ltile(sb + S_L(0), ((c + d0) & 127) * 128, tid);
        CPC();
        if (len > 1) {
            load_ftile(sb + S_K(1), ((c + d0 + 1) & 127) * 128, tid);
            load_ltile(sb + S_L(1), ((c + d0 + 1) & 127) * 128, tid);
            CPC();
            CPW(2);
        } else {
            CPW(1);
        }
        __syncthreads();

        uint32_t A[8][4];
#pragma unroll
        for (int s = 0; s < 8; s++) {
            int ch = 2 * s + hbit;
            uint32_t cA = (uint32_t)(((ch >> 3) * 16384) + ((((uint32_t)(ch & 7) ^ ax) << 4)));
            ldsm4(A[s], sb + S_Q + aR + cA);
        }
        uint32_t LC[8][4];
#pragma unroll
        for (int s = 0; s < 8; s++) ldsm4t(LC[s], sb + S_LC + lOff + (uint32_t)(s * 768));

        float O0[4] = {0.f, 0.f, 0.f, 0.f};
        float O1[4] = {0.f, 0.f, 0.f, 0.f};

        for (int i = 0; i < len; i++) {
            int d = d0 + i;
            int kb = i % 3, wb = i & 1;
            int j = (c + d) & 127;
            if (i + 2 < len) {
                int jn = (c + d + 2) & 127;
                load_ftile(sb + S_K((i + 2) % 3), jn * 128, tid);
                load_ltile(sb + S_L((i + 2) % 3), jn * 128, tid);
                CPC();
                CPW(2);
            } else if (i + 1 < len) {
                CPW(1);
            } else {
                CPW(0);
            }
            uint32_t KH = sb + S_K(kb) + bR;
            uint32_t Lb = sb + (uint32_t)S_L(kb) + lOff;
            uint32_t WB = sb + (uint32_t)S_W(wb);

#pragma unroll
            for (int p = 0; p < 8; p++) {
                float S0[4] = {0.f, 0.f, 0.f, 0.f};
                float S1[4] = {0.f, 0.f, 0.f, 0.f};
                uint32_t kbad = KH + (uint32_t)(p * 2048);
#pragma unroll
                for (int s = 0; s < 8; s++) {
                    uint32_t bb[4];
                    ldsm4(bb, kbad + cB[s]);
                    mmaf16(S0, A[s], bb[0], bb[2]);
                    mmaf16(S1, A[s], bb[1], bb[3]);
                }
                uint32_t W[4];
                W[0] = packh(ex2a(S0[0] * C), ex2a(S0[1] * C));
                W[1] = packh(ex2a(S0[2] * C), ex2a(S0[3] * C));
                W[2] = packh(ex2a(S1[0] * C), ex2a(S1[1] * C));
                W[3] = packh(ex2a(S1[2] * C), ex2a(S1[3] * C));
                uint32_t bf[4];
                ldsm4t(bf, Lb + (uint32_t)(p * 768));
                mmaf16(O0, W, bf[0], bf[2]);
                mmaf16(O1, W, bf[1], bf[3]);
                sts32(WB + swoff(rW, 2 * p) + wIn,         W[0]);
                sts32(WB + swoff(rW + 8, 2 * p) + wIn,     W[1]);
                sts32(WB + swoff(rW, 2 * p + 1) + wIn,     W[2]);
                sts32(WB + swoff(rW + 8, 2 * p + 1) + wIn, W[3]);
            }

            __syncthreads();   // W(d) complete; ring(d) reads done

            if (d > 0) {
                float F0[4] = {0.f, 0.f, 0.f, 0.f};
                float F1[4] = {0.f, 0.f, 0.f, 0.f};
#pragma unroll
                for (int s = 0; s < 8; s++) {
                    uint32_t At[4];
                    ldsm4t(At, WB + swoff(16 * s + qbase, chW));
                    mmaf16(F0, At, LC[s][0], LC[s][2]);
                    mmaf16(F1, At, LC[s][1], LC[s][3]);
                }
                int slot = (d < 64) ? (d - 1) : 63;
                int krow = 16 * wid + (lane >> 2);
                int cp = 2 * (lane & 3);
                float* pb = g_part + (((size_t)j * NSLOT + slot) * 128 + krow) * 12;
                *(float2*)(pb + cp)          = make_float2(F0[0], F0[1]);
                *(float2*)(pb + 8 * 12 + cp) = make_float2(F0[2], F0[3]);
                if ((lane & 3) < 2) {
                    *(float2*)(pb + 8 + cp)          = make_float2(F1[0], F1[1]);
                    *(float2*)(pb + 8 * 12 + 8 + cp) = make_float2(F1[2], F1[3]);
                }
            }
        }

        // flush local partial -> slot lslot of row-block c
        {
            int qrow = 16 * wid + (lane >> 2);
            int cp = 2 * (lane & 3);
            float* pb = g_part + (((size_t)c * NSLOT + lslot) * 128 + qrow) * 12;
            *(float2*)(pb + cp)          = make_float2(O0[0], O0[1]);
            *(float2*)(pb + 8 * 12 + cp) = make_float2(O0[2], O0[3]);
            if ((lane & 3) < 2) {
                *(float2*)(pb + 8 + cp)          = make_float2(O1[0], O1[1]);
                *(float2*)(pb + 8 * 12 + 8 + cp) = make_float2(O1[2], O1[3]);
            }
        }

        if (bid < 128) break;
        t += len;
        if (t >= tend) break;
    }
}

// ---------------- reduction: 2 CTAs per row-block, one float4 per thread ----------------
__global__ void __launch_bounds__(192) k_red(float* __restrict__ out) {
    __shared__ float den[64];
    __shared__ float sInv[NC];
    int j = blockIdx.x >> 1, half = blockIdx.x & 1, tid = threadIdx.x;
    if (tid == 0) {
        float tot = 0.f;
#pragma unroll
        for (int q = 0; q < NC; q++) tot += g_cnt[q];
#pragma unroll
        for (int q = 0; q < NC; q++) {
            float dd = g_cnt[q];
            sInv[q] = 1.f / ((dd == 0.f) ? tot : dd);
        }
    }
    int i4 = half * 192 + tid;               // 0..383 float4 within a slot row-block
    const float4* base = reinterpret_cast<const float4*>(g_part) + (size_t)j * NSLOT * 384;
    float4 s0 = f4add(base[(size_t)64 * 384 + i4],
                      f4add(base[(size_t)65 * 384 + i4], base[(size_t)66 * 384 + i4]));
    float4 s1 = make_float4(0.f, 0.f, 0.f, 0.f);
    int nf = 63 + ((j >= 64) ? 1 : 0);
    int sl = 0;
    for (; sl + 2 <= nf; sl += 2) {
        s0 = f4add(s0, base[(size_t)sl * 384 + i4]);
        s1 = f4add(s1, base[(size_t)(sl + 1) * 384 + i4]);
    }
    if (sl < nf) s0 = f4add(s0, base[(size_t)sl * 384 + i4]);
    s0 = f4add(s0, s1);

    int row = i4 / 3, part = i4 - row * 3;   // 12 floats = 3 float4 per row
    if (part == 2) den[row & 63] = s0.z;     // col 10 = denominator
    __syncthreads();
    float dv = 1.f / den[row & 63];
    float* op = out + ((size_t)j * 128 + row) * NC;
    if (part == 0) {
        op[0] = s0.x * dv * sInv[0]; op[1] = s0.y * dv * sInv[1];
        op[2] = s0.z * dv * sInv[2]; op[3] = s0.w * dv * sInv[3];
    } else if (part == 1) {
        op[4] = s0.x * dv * sInv[4]; op[5] = s0.y * dv * sInv[5];
        op[6] = s0.z * dv * sInv[6]; op[7] = s0.w * dv * sInv[7];
    } else {
        op[8] = s0.x * dv * sInv[8]; op[9] = s0.y * dv * sInv[9];
    }
}

// ---------------- launcher ----------------
extern "C" void kernel_launch(void* const* d_in, const int* in_sizes, int n_in,
                              void* d_out, int out_size) {
    const float* anchor   = (const float*)d_in[0];
    const float* positive = (const float*)d_in[1];
    const float* lb_feat  = (const float*)d_in[2];
    const float* lb_oh    = (const float*)d_in[3];
    const float* logits1  = (const float*)d_in[4];
    const float* logits2  = (const float*)d_in[5];
    float* out = (float*)d_out;

    int dev = 0, sm = 148;
    cudaGetDevice(&dev);
    cudaDeviceGetAttribute(&sm, cudaDevAttrMultiProcessorCount, dev);
    int H = (sm > 128) ? (sm - 128) : 0;
    if (H > 64) H = 64;
    int m = (H > 0) ? (TTOT + (128 + H) - 1) / (128 + H) : 65;
    if (H > 0 && m > 64) m = 64;

    cudaFuncSetAttribute(k_attn, cudaFuncAttributeMaxDynamicSharedMemorySize, SMEM_REQ);

    k_norm<<<(NTOT * 32) / 256, 256>>>(lb_feat, anchor, positive);
    k_prep<<<40, 256>>>(lb_oh, logits1, logits2);
    k_attn<<<128 + H, 256, SMEM_REQ>>>(m);
    k_red<<<256, 192>>>(out);
}

// round 14
// speedup vs baseline: 1.2870x; 1.0110x over previous
#include <cuda_runtime.h>
#include <cuda_fp16.h>
#include <cstdint>

#define NTOT 16384
#define BLB  4096
#define BULB 6144
#define DIM  128
#define NC   10
#define LSTB 24
#define TTOT 8256   // 64*65 + 64*64 symmetric tiles

// ---------------- device scratch ----------------
__device__ __align__(256) __half g_F[NTOT * DIM];
__device__ __align__(256) __half g_Lh[NTOT * LSTB];     // 10 probs, [10]=1, rest 0
__device__ __align__(256) float g_acc[128 * 128 * 12];  // 768 KB accumulator (L2-resident)
__device__ float g_cnt[NC];

// ---------------- helpers ----------------
__device__ __forceinline__ float ex2a(float x) {
    float y; asm("ex2.approx.ftz.f32 %0,%1;" : "=f"(y) : "f"(x)); return y;
}
__device__ __forceinline__ void cpa16(uint32_t dst, const void* src) {
    asm volatile("cp.async.cg.shared.global [%0], [%1], 16;" :: "r"(dst), "l"(src));
}
#define CPC()  asm volatile("cp.async.commit_group;" ::: "memory")
#define CPW(n) asm volatile("cp.async.wait_group %0;" :: "n"(n) : "memory")

__device__ __forceinline__ void ldsm4(uint32_t* r, uint32_t a) {
    asm volatile("ldmatrix.sync.aligned.m8n8.x4.shared.b16 {%0,%1,%2,%3},[%4];"
        : "=r"(r[0]), "=r"(r[1]), "=r"(r[2]), "=r"(r[3]) : "r"(a));
}
__device__ __forceinline__ void ldsm4t(uint32_t* r, uint32_t a) {
    asm volatile("ldmatrix.sync.aligned.m8n8.x4.trans.shared.b16 {%0,%1,%2,%3},[%4];"
        : "=r"(r[0]), "=r"(r[1]), "=r"(r[2]), "=r"(r[3]) : "r"(a));
}
__device__ __forceinline__ void mmaf16(float* d, const uint32_t* a, uint32_t b0, uint32_t b1) {
    asm volatile("mma.sync.aligned.m16n8k16.row.col.f32.f16.f16.f32 "
        "{%0,%1,%2,%3},{%4,%5,%6,%7},{%8,%9},{%0,%1,%2,%3};"
        : "+f"(d[0]), "+f"(d[1]), "+f"(d[2]), "+f"(d[3])
        : "r"(a[0]), "r"(a[1]), "r"(a[2]), "r"(a[3]), "r"(b0), "r"(b1));
}
__device__ __forceinline__ uint32_t packh(float lo, float hi) {
    uint32_t r; asm("cvt.rn.f16x2.f32 %0, %1, %2;" : "=r"(r) : "f"(hi), "f"(lo)); return r;
}
__device__ __forceinline__ void sts32(uint32_t a, uint32_t v) {
    asm volatile("st.shared.b32 [%0],%1;" :: "r"(a), "r"(v) : "memory");
}

// ---------------- smem layout (byte offsets from 1024-aligned base) ----------------
#define S_Q     0
#define S_K(b)  (32768 + (b) * 32768)      // 3 buffers
#define S_W(b)  (131072 + (b) * 32768)     // 2 buffers
#define S_L(b)  (196608 + (b) * 6144)      // 3 buffers
#define S_LC    215040                     // L_c copy for trans PV
#define SMEM_REQ (221184 + 1024)

// SW128 blocked layout for a 128x128 fp16 tile (row 0..127, 16B-chunk 0..15)
__device__ __forceinline__ uint32_t swoff(int row, int ch) {
    return (uint32_t)(((row >> 3) * 1024) + ((ch >> 3) * 16384)
                      + ((row & 7) * 128) + ((((ch & 7) ^ (row & 7)) << 4)));
}

__device__ __forceinline__ void load_ftile(uint32_t dst, int rowbase, int tid) {
#pragma unroll
    for (int i = 0; i < 8; i++) {
        int idx = i * 256 + tid;
        int row = idx >> 4, ch = idx & 15;
        cpa16(dst + swoff(row, ch), g_F + (size_t)(rowbase + row) * DIM + ch * 8);
    }
}
__device__ __forceinline__ void load_ltile(uint32_t dst, int rowbase, int tid) {
#pragma unroll
    for (int i = 0; i < 2; i++) {
        int idx = i * 256 + tid;
        if (idx < 384) {
            int row = idx / 3, part = idx - row * 3;
            cpa16(dst + (uint32_t)(row * 48 + part * 16),
                  g_Lh + (size_t)(rowbase + row) * LSTB + part * 8);
        }
    }
}

// ---------------- prep: normalize + zero counters/accumulator ----------------
__global__ void k_norm(const float* __restrict__ lb, const float* __restrict__ an,
                       const float* __restrict__ po) {
    int gt = blockIdx.x * blockDim.x + threadIdx.x;
    if (gt < NC) g_cnt[gt] = 0.f;
    if (gt < 128 * 128 * 12) g_acc[gt] = 0.f;
    int w = gt >> 5;
    int ln = threadIdx.x & 31;
    if (w >= NTOT) return;
    const float* s = (w < BLB) ? lb + (size_t)w * DIM
                   : (w < BLB + BULB) ? an + (size_t)(w - BLB) * DIM
                                      : po + (size_t)(w - BLB - BULB) * DIM;
    float4 v = ((const float4*)s)[ln];
    float q = v.x*v.x + v.y*v.y + v.z*v.z + v.w*v.w;
#pragma unroll
    for (int o = 16; o; o >>= 1) q += __shfl_xor_sync(0xffffffffu, q, o);
    float iv = 1.f / fmaxf(sqrtf(q), 1e-12f);
    __half2 h0 = __floats2half2_rn(v.x * iv, v.y * iv);
    __half2 h1 = __floats2half2_rn(v.z * iv, v.w * iv);
    size_t base = (size_t)w * DIM + ln * 4;
    *(__half2*)(g_F + base)     = h0;
    *(__half2*)(g_F + base + 2) = h1;
}

// ---------------- prep: labeled + unlabeled logits (fused) ----------------
__global__ void __launch_bounds__(256) k_prep(const float* __restrict__ oh,
                                              const float* __restrict__ l1,
                                              const float* __restrict__ l2) {
    int bid = blockIdx.x, tid = threadIdx.x;
    if (bid < 16) {
        int r = bid * 256 + tid;
#pragma unroll
        for (int c = 0; c < NC; c++) {
            float v = oh[r * NC + c];
            g_Lh[r * LSTB + c] = __float2half(v);
            if (v != 0.f) atomicAdd(&g_cnt[c], v);
        }
        g_Lh[r * LSTB + 10] = __float2half(1.0f);
#pragma unroll
        for (int c = 11; c < LSTB; c++) g_Lh[r * LSTB + c] = __float2half(0.0f);
        return;
    }
    int r = (bid - 16) * 256 + tid;
    float a[NC], b[NC];
#pragma unroll
    for (int i = 0; i < NC; i++) { a[i] = l1[r*NC+i]; b[i] = l2[r*NC+i]; }
    float m1 = -1e30f, m2 = -1e30f;
#pragma unroll
    for (int i = 0; i < NC; i++) { m1 = fmaxf(m1, a[i]); m2 = fmaxf(m2, b[i]); }
    float s1 = 0.f, s2 = 0.f;
#pragma unroll
    for (int i = 0; i < NC; i++) { s1 += expf(2.f*(a[i]-m1)); s2 += expf(2.f*(b[i]-m2)); }
    bool take1 = (s1 <= s2);
    float lg[NC];
#pragma unroll
    for (int i = 0; i < NC; i++) lg[i] = take1 ? a[i] : b[i];

    float m = -1e30f;
#pragma unroll
    for (int i = 0; i < NC; i++) m = fmaxf(m, lg[i]);
    float e[NC], s = 0.f;
#pragma unroll
    for (int i = 0; i < NC; i++) { e[i] = expf(lg[i]-m); s += e[i]; }
#pragma unroll
    for (int i = 0; i < NC; i++) if (e[i] < 0.95f * s) lg[i] = 0.f;

    float mx = lg[0]; int idx = 0;
#pragma unroll
    for (int i = 1; i < NC; i++) if (lg[i] > mx) { mx = lg[i]; idx = i; }
    if (mx != 0.f) atomicAdd(&g_cnt[idx], 2.f);

    float mm = -1e30f;
#pragma unroll
    for (int i = 0; i < NC; i++) mm = fmaxf(mm, lg[i]);
    float p[NC], ss = 0.f;
#pragma unroll
    for (int i = 0; i < NC; i++) { p[i] = expf(2.f*(lg[i]-mm)); ss += p[i]; }
    float inv = 1.f / ss;
    int r1 = BLB + r, r2 = BLB + BULB + r;
#pragma unroll
    for (int c = 0; c < NC; c++) {
        __half v = __float2half(p[c] * inv);
        g_Lh[r1*LSTB + c] = v; g_Lh[r2*LSTB + c] = v;
    }
    g_Lh[r1*LSTB + 10] = __float2half(1.0f);
    g_Lh[r2*LSTB + 10] = __float2half(1.0f);
#pragma unroll
    for (int c = 11; c < LSTB; c++) {
        g_Lh[r1*LSTB + c] = __float2half(0.0f);
        g_Lh[r2*LSTB + c] = __float2half(0.0f);
    }
}

// ---------------- main attention: symmetric tiles, 128 mains + H helpers ----------------
// Main CTA c: tiles (c, c+d) d=0..m-1. Helper CTAs split the c-major tail list.
// All partial outputs merge into g_acc via atomicAdd (no contention by schedule).
__global__ void __launch_bounds__(256, 1) k_attn(int m) {
    extern __shared__ char smraw[];
    uint32_t sb0;
    asm("{\n.reg .u64 t;\ncvta.to.shared.u64 t, %1;\ncvt.u32.u64 %0, t;\n}" : "=r"(sb0) : "l"(smraw));
    uint32_t sb = (sb0 + 1023u) & ~1023u;

    int tid = threadIdx.x, wid = tid >> 5, lane = tid & 31;
    int lr = lane & 7, lg = lane >> 3;
    int hbit = lg >> 1;
    int rbit = lg & 1;
    int bid = blockIdx.x;
    int H = (int)gridDim.x - 128;

    // lane-constant address components (c-independent)
    int row_a = 16 * wid + rbit * 8 + lr;
    uint32_t aR = (uint32_t)(((row_a >> 3) * 1024) + ((row_a & 7) * 128));
    uint32_t ax = (uint32_t)(row_a & 7);
    int r0 = rbit * 8 + lr;
    uint32_t bR = (uint32_t)(((r0 >> 3) * 1024) + ((r0 & 7) * 128));
    uint32_t bx = (uint32_t)(r0 & 7);
    uint32_t lOff = (uint32_t)((hbit * 8 + lr) * 48 + rbit * 16);
    uint32_t cB[8];
#pragma unroll
    for (int s = 0; s < 8; s++) {
        int ch = 2 * s + hbit;
        cB[s] = (uint32_t)(((ch >> 3) * 16384) + ((((uint32_t)(ch & 7) ^ bx) << 4)));
    }
    int rW = 16 * wid + (lane >> 2);
    uint32_t wIn = (uint32_t)(4 * (lane & 3));
    int qbase = ((lane >> 4) << 3) + (lane & 7);
    int chW = 2 * wid + ((lane >> 3) & 1);
    const float C = 2.8853900817779268f;   // 2/ln2

    int A1 = 65 - m, A2 = 64 - m, tail = TTOT - 128 * m;
    int t = 0, tend = 0;
    if (bid >= 128) {
        int q = (tail + H - 1) / H;
        t = (bid - 128) * q;
        tend = min(tail, t + q);
        if (t >= tend) return;
    }

    for (;;) {   // segment loop
        int c, d0, len;
        if (bid < 128) {
            c = bid; d0 = 0;
            len = (H > 0) ? m : ((c < 64) ? 65 : 64);
        } else {
            int b1 = 64 * A1;
            if (t < b1) { c = t / A1; int o = t - c * A1; d0 = m + o; len = A1 - o; }
            else { int u = t - b1; int cc = u / A2; c = 64 + cc; int o = u - cc * A2; d0 = m + o; len = A2 - o; }
            if (len > tend - t) len = tend - t;
        }

        // segment prologue: G0={Q,LC}, G1={K(d0),L(d0)}, G2={K(d0+1),L(d0+1)}
        load_ftile(sb + S_Q, c * 128, tid);
        load_ltile(sb + S_LC, c * 128, tid);
        CPC();
        load_ftile(sb + S_K(0), ((c + d0) & 127) * 128, tid);
        load_ltile(sb + S_L(0), ((c + d0) & 127) * 128, tid);
        CPC();
        if (len > 1) {
            load_ftile(sb + S_K(1), ((c + d0 + 1) & 127) * 128, tid);
            load_ltile(sb + S_L(1), ((c + d0 + 1) & 127) * 128, tid);
            CPC();
            CPW(2);
        } else {
            CPW(1);
        }
        __syncthreads();

        uint32_t A[8][4];
#pragma unroll
        for (int s = 0; s < 8; s++) {
            int ch = 2 * s + hbit;
            uint32_t cA = (uint32_t)(((ch >> 3) * 16384) + ((((uint32_t)(ch & 7) ^ ax) << 4)));
            ldsm4(A[s], sb + S_Q + aR + cA);
        }
        uint32_t LC[8][4];
#pragma unroll
        for (int s = 0; s < 8; s++) ldsm4t(LC[s], sb + S_LC + lOff + (uint32_t)(s * 768));

        float O0[4] = {0.f, 0.f, 0.f, 0.f};
        float O1[4] = {0.f, 0.f, 0.f, 0.f};

        for (int i = 0; i < len; i++) {
            int d = d0 + i;
            int kb = i % 3, wb = i & 1;
            int j = (c + d) & 127;
            if (i + 2 < len) {
                int jn = (c + d + 2) & 127;
                load_ftile(sb + S_K((i + 2) % 3), jn * 128, tid);
                load_ltile(sb + S_L((i + 2) % 3), jn * 128, tid);
                CPC();
                CPW(2);
            } else if (i + 1 < len) {
                CPW(1);
            } else {
                CPW(0);
            }
            uint32_t KH = sb + S_K(kb) + bR;
            uint32_t Lb = sb + (uint32_t)S_L(kb) + lOff;
            uint32_t WB = sb + (uint32_t)S_W(wb);

#pragma unroll
            for (int p = 0; p < 8; p++) {
                float S0[4] = {0.f, 0.f, 0.f, 0.f};
                float S1[4] = {0.f, 0.f, 0.f, 0.f};
                uint32_t kbad = KH + (uint32_t)(p * 2048);
#pragma unroll
                for (int s = 0; s < 8; s++) {
                    uint32_t bb[4];
                    ldsm4(bb, kbad + cB[s]);
                    mmaf16(S0, A[s], bb[0], bb[2]);
                    mmaf16(S1, A[s], bb[1], bb[3]);
                }
                uint32_t W[4];
                W[0] = packh(ex2a(S0[0] * C), ex2a(S0[1] * C));
                W[1] = packh(ex2a(S0[2] * C), ex2a(S0[3] * C));
                W[2] = packh(ex2a(S1[0] * C), ex2a(S1[1] * C));
                W[3] = packh(ex2a(S1[2] * C), ex2a(S1[3] * C));
                uint32_t bf[4];
                ldsm4t(bf, Lb + (uint32_t)(p * 768));
                mmaf16(O0, W, bf[0], bf[2]);
                mmaf16(O1, W, bf[1], bf[3]);
                sts32(WB + swoff(rW, 2 * p) + wIn,         W[0]);
                sts32(WB + swoff(rW + 8, 2 * p) + wIn,     W[1]);
                sts32(WB + swoff(rW, 2 * p + 1) + wIn,     W[2]);
                sts32(WB + swoff(rW + 8, 2 * p + 1) + wIn, W[3]);
            }

            __syncthreads();   // W(d) complete; ring(d) reads done

            if (d > 0) {
                float F0[4] = {0.f, 0.f, 0.f, 0.f};
                float F1[4] = {0.f, 0.f, 0.f, 0.f};
#pragma unroll
                for (int s = 0; s < 8; s++) {
                    uint32_t At[4];
                    ldsm4t(At, WB + swoff(16 * s + qbase, chW));
                    mmaf16(F0, At, LC[s][0], LC[s][2]);
                    mmaf16(F1, At, LC[s][1], LC[s][3]);
                }
                int krow = 16 * wid + (lane >> 2);
                int cp = 2 * (lane & 3);
                float* pb = g_acc + ((size_t)j * 128 + krow) * 12;
                atomicAdd(pb + cp,          F0[0]);
                atomicAdd(pb + cp + 1,      F0[1]);
                atomicAdd(pb + 96 + cp,     F0[2]);
                atomicAdd(pb + 96 + cp + 1, F0[3]);
                if ((lane & 3) < 2) {
                    atomicAdd(pb + 8 + cp,          F1[0]);
                    atomicAdd(pb + 8 + cp + 1,      F1[1]);
                    atomicAdd(pb + 96 + 8 + cp,     F1[2]);
                    atomicAdd(pb + 96 + 8 + cp + 1, F1[3]);
                }
            }
        }

        // flush local partial into row-block c
        {
            int qrow = 16 * wid + (lane >> 2);
            int cp = 2 * (lane & 3);
            float* pb = g_acc + ((size_t)c * 128 + qrow) * 12;
            atomicAdd(pb + cp,          O0[0]);
            atomicAdd(pb + cp + 1,      O0[1]);
            atomicAdd(pb + 96 + cp,     O0[2]);
            atomicAdd(pb + 96 + cp + 1, O0[3]);
            if ((lane & 3) < 2) {
                atomicAdd(pb + 8 + cp,          O1[0]);
                atomicAdd(pb + 8 + cp + 1,      O1[1]);
                atomicAdd(pb + 96 + 8 + cp,     O1[2]);
                atomicAdd(pb + 96 + 8 + cp + 1, O1[3]);
            }
        }

        if (bid < 128) break;
        t += len;
        if (t >= tend) break;
    }
}

// ---------------- reduction: divide + class-scale (768 KB read) ----------------
__global__ void __launch_bounds__(128) k_red(float* __restrict__ out) {
    __shared__ float sInv[NC];
    int j = blockIdx.x, tid = threadIdx.x;
    if (tid == 0) {
        float tot = 0.f;
#pragma unroll
        for (int q = 0; q < NC; q++) tot += g_cnt[q];
#pragma unroll
        for (int q = 0; q < NC; q++) {
            float dd = g_cnt[q];
            sInv[q] = 1.f / ((dd == 0.f) ? tot : dd);
        }
    }
    __syncthreads();
    const float* ar = g_acc + ((size_t)j * 128 + tid) * 12;
    float4 a = *(const float4*)ar;
    float4 b = *(const float4*)(ar + 4);
    float4 cq = *(const float4*)(ar + 8);
    float dv = 1.f / cq.z;                 // col 10 = denominator
    float* op = out + ((size_t)j * 128 + tid) * NC;
    op[0] = a.x * dv * sInv[0]; op[1] = a.y * dv * sInv[1];
    op[2] = a.z * dv * sInv[2]; op[3] = a.w * dv * sInv[3];
    op[4] = b.x * dv * sInv[4]; op[5] = b.y * dv * sInv[5];
    op[6] = b.z * dv * sInv[6]; op[7] = b.w * dv * sInv[7];
    op[8] = cq.x * dv * sInv[8]; op[9] = cq.y * dv * sInv[9];
}

// ---------------- launcher ----------------
extern "C" void kernel_launch(void* const* d_in, const int* in_sizes, int n_in,
                              void* d_out, int out_size) {
    const float* anchor   = (const float*)d_in[0];
    const float* positive = (const float*)d_in[1];
    const float* lb_feat  = (const float*)d_in[2];
    const float* lb_oh    = (const float*)d_in[3];
    const float* logits1  = (const float*)d_in[4];
    const float* logits2  = (const float*)d_in[5];
    float* out = (float*)d_out;

    int dev = 0, sm = 148;
    cudaGetDevice(&dev);
    cudaDeviceGetAttribute(&sm, cudaDevAttrMultiProcessorCount, dev);
    int H = (sm > 128) ? (sm - 128) : 0;
    if (H > 64) H = 64;
    int m = (H > 0) ? (TTOT + (128 + H) - 1) / (128 + H) : 65;
    if (H > 0 && m > 64) m = 64;

    cudaFuncSetAttribute(k_attn, cudaFuncAttributeMaxDynamicSharedMemorySize, SMEM_REQ);

    k_norm<<<(NTOT * 32) / 256, 256>>>(lb_feat, anchor, positive);
    k_prep<<<40, 256>>>(lb_oh, logits1, logits2);
    k_attn<<<128 + H, 256, SMEM_REQ>>>(m);
    k_red<<<128, 128>>>(out);
}

// round 15
// speedup vs baseline: 1.3621x; 1.0583x over previous
#include <cuda_runtime.h>
#include <cuda_fp16.h>
#include <cstdint>

#define NTOT 16384
#define BLB  4096
#define BULB 6144
#define DIM  128
#define NC   10
#define LSTB 24
#define TTOT 8256   // 64*65 + 64*64 symmetric tiles

// ---------------- device scratch ----------------
__device__ __align__(256) __half g_F[NTOT * DIM];
__device__ __align__(256) __half g_Lh[NTOT * LSTB];     // 10 probs, [10]=1, rest 0
__device__ __align__(256) float g_acc[128 * 128 * 12];  // 768 KB accumulator (L2-resident)
__device__ float g_cnt[NC];

// ---------------- helpers ----------------
__device__ __forceinline__ float ex2a(float x) {
    float y; asm("ex2.approx.ftz.f32 %0,%1;" : "=f"(y) : "f"(x)); return y;
}
__device__ __forceinline__ void cpa16(uint32_t dst, const void* src) {
    asm volatile("cp.async.cg.shared.global [%0], [%1], 16;" :: "r"(dst), "l"(src));
}
#define CPC()  asm volatile("cp.async.commit_group;" ::: "memory")
#define CPW(n) asm volatile("cp.async.wait_group %0;" :: "n"(n) : "memory")

__device__ __forceinline__ void ldsm4(uint32_t* r, uint32_t a) {
    asm volatile("ldmatrix.sync.aligned.m8n8.x4.shared.b16 {%0,%1,%2,%3},[%4];"
        : "=r"(r[0]), "=r"(r[1]), "=r"(r[2]), "=r"(r[3]) : "r"(a));
}
__device__ __forceinline__ void ldsm4t(uint32_t* r, uint32_t a) {
    asm volatile("ldmatrix.sync.aligned.m8n8.x4.trans.shared.b16 {%0,%1,%2,%3},[%4];"
        : "=r"(r[0]), "=r"(r[1]), "=r"(r[2]), "=r"(r[3]) : "r"(a));
}
__device__ __forceinline__ void mmaf16(float* d, const uint32_t* a, uint32_t b0, uint32_t b1) {
    asm volatile("mma.sync.aligned.m16n8k16.row.col.f32.f16.f16.f32 "
        "{%0,%1,%2,%3},{%4,%5,%6,%7},{%8,%9},{%0,%1,%2,%3};"
        : "+f"(d[0]), "+f"(d[1]), "+f"(d[2]), "+f"(d[3])
        : "r"(a[0]), "r"(a[1]), "r"(a[2]), "r"(a[3]), "r"(b0), "r"(b1));
}
__device__ __forceinline__ uint32_t packh(float lo, float hi) {
    uint32_t r; asm("cvt.rn.f16x2.f32 %0, %1, %2;" : "=r"(r) : "f"(hi), "f"(lo)); return r;
}
__device__ __forceinline__ void sts32(uint32_t a, uint32_t v) {
    asm volatile("st.shared.b32 [%0],%1;" :: "r"(a), "r"(v) : "memory");
}
__device__ __forceinline__ void red2(float* p, float x, float y) {
    atomicAdd(reinterpret_cast<float2*>(p), make_float2(x, y));   // RED.E.ADD.F32x2
}

// ---------------- smem layout (byte offsets from 1024-aligned base) ----------------
#define S_Q     0
#define S_K(b)  (32768 + (b) * 32768)      // 3 buffers
#define S_W(b)  (131072 + (b) * 32768)     // 2 buffers
#define S_L(b)  (196608 + (b) * 6144)      // 3 buffers
#define S_LC    215040                     // L_c copy for trans PV
#define SMEM_REQ (221184 + 1024)

// SW128 blocked layout for a 128x128 fp16 tile (row 0..127, 16B-chunk 0..15)
__device__ __forceinline__ uint32_t swoff(int row, int ch) {
    return (uint32_t)(((row >> 3) * 1024) + ((ch >> 3) * 16384)
                      + ((row & 7) * 128) + ((((ch & 7) ^ (row & 7)) << 4)));
}

__device__ __forceinline__ void load_ftile(uint32_t dst, int rowbase, int tid) {
#pragma unroll
    for (int i = 0; i < 8; i++) {
        int idx = i * 256 + tid;
        int row = idx >> 4, ch = idx & 15;
        cpa16(dst + swoff(row, ch), g_F + (size_t)(rowbase + row) * DIM + ch * 8);
    }
}
__device__ __forceinline__ void load_ltile(uint32_t dst, int rowbase, int tid) {
#pragma unroll
    for (int i = 0; i < 2; i++) {
        int idx = i * 256 + tid;
        if (idx < 384) {
            int row = idx / 3, part = idx - row * 3;
            cpa16(dst + (uint32_t)(row * 48 + part * 16),
                  g_Lh + (size_t)(rowbase + row) * LSTB + part * 8);
        }
    }
}

// ---------------- prep: normalize + zero counters/accumulator ----------------
__global__ void k_norm(const float* __restrict__ lb, const float* __restrict__ an,
                       const float* __restrict__ po) {
    int gt = blockIdx.x * blockDim.x + threadIdx.x;
    if (gt < NC) g_cnt[gt] = 0.f;
    if (gt < 128 * 128 * 12) g_acc[gt] = 0.f;
    int w = gt >> 5;
    int ln = threadIdx.x & 31;
    if (w >= NTOT) return;
    const float* s = (w < BLB) ? lb + (size_t)w * DIM
                   : (w < BLB + BULB) ? an + (size_t)(w - BLB) * DIM
                                      : po + (size_t)(w - BLB - BULB) * DIM;
    float4 v = ((const float4*)s)[ln];
    float q = v.x*v.x + v.y*v.y + v.z*v.z + v.w*v.w;
#pragma unroll
    for (int o = 16; o; o >>= 1) q += __shfl_xor_sync(0xffffffffu, q, o);
    float iv = 1.f / fmaxf(sqrtf(q), 1e-12f);
    __half2 h0 = __floats2half2_rn(v.x * iv, v.y * iv);
    __half2 h1 = __floats2half2_rn(v.z * iv, v.w * iv);
    size_t base = (size_t)w * DIM + ln * 4;
    *(__half2*)(g_F + base)     = h0;
    *(__half2*)(g_F + base + 2) = h1;
}

// ---------------- prep: labeled + unlabeled logits (fused) ----------------
__global__ void __launch_bounds__(256) k_prep(const float* __restrict__ oh,
                                              const float* __restrict__ l1,
                                              const float* __restrict__ l2) {
    int bid = blockIdx.x, tid = threadIdx.x;
    if (bid < 16) {
        int r = bid * 256 + tid;
#pragma unroll
        for (int c = 0; c < NC; c++) {
            float v = oh[r * NC + c];
            g_Lh[r * LSTB + c] = __float2half(v);
            if (v != 0.f) atomicAdd(&g_cnt[c], v);
        }
        g_Lh[r * LSTB + 10] = __float2half(1.0f);
#pragma unroll
        for (int c = 11; c < LSTB; c++) g_Lh[r * LSTB + c] = __float2half(0.0f);
        return;
    }
    int r = (bid - 16) * 256 + tid;
    float a[NC], b[NC];
#pragma unroll
    for (int i = 0; i < NC; i++) { a[i] = l1[r*NC+i]; b[i] = l2[r*NC+i]; }
    float m1 = -1e30f, m2 = -1e30f;
#pragma unroll
    for (int i = 0; i < NC; i++) { m1 = fmaxf(m1, a[i]); m2 = fmaxf(m2, b[i]); }
    float s1 = 0.f, s2 = 0.f;
#pragma unroll
    for (int i = 0; i < NC; i++) { s1 += expf(2.f*(a[i]-m1)); s2 += expf(2.f*(b[i]-m2)); }
    bool take1 = (s1 <= s2);
    float lg[NC];
#pragma unroll
    for (int i = 0; i < NC; i++) lg[i] = take1 ? a[i] : b[i];

    float m = -1e30f;
#pragma unroll
    for (int i = 0; i < NC; i++) m = fmaxf(m, lg[i]);
    float e[NC], s = 0.f;
#pragma unroll
    for (int i = 0; i < NC; i++) { e[i] = expf(lg[i]-m); s += e[i]; }
#pragma unroll
    for (int i = 0; i < NC; i++) if (e[i] < 0.95f * s) lg[i] = 0.f;

    float mx = lg[0]; int idx = 0;
#pragma unroll
    for (int i = 1; i < NC; i++) if (lg[i] > mx) { mx = lg[i]; idx = i; }
    if (mx != 0.f) atomicAdd(&g_cnt[idx], 2.f);

    float mm = -1e30f;
#pragma unroll
    for (int i = 0; i < NC; i++) mm = fmaxf(mm, lg[i]);
    float p[NC], ss = 0.f;
#pragma unroll
    for (int i = 0; i < NC; i++) { p[i] = expf(2.f*(lg[i]-mm)); ss += p[i]; }
    float inv = 1.f / ss;
    int r1 = BLB + r, r2 = BLB + BULB + r;
#pragma unroll
    for (int c = 0; c < NC; c++) {
        __half v = __float2half(p[c] * inv);
        g_Lh[r1*LSTB + c] = v; g_Lh[r2*LSTB + c] = v;
    }
    g_Lh[r1*LSTB + 10] = __float2half(1.0f);
    g_Lh[r2*LSTB + 10] = __float2half(1.0f);
#pragma unroll
    for (int c = 11; c < LSTB; c++) {
        g_Lh[r1*LSTB + c] = __float2half(0.0f);
        g_Lh[r2*LSTB + c] = __float2half(0.0f);
    }
}

// ---------------- main attention: symmetric tiles, 128 mains + H helpers ----------------
// Main CTA c: tiles (c, c+d) d=0..m-1. Helper CTAs split the c-major tail list.
// All partial outputs merge into g_acc via float2 atomicAdd (RED.F32x2).
__global__ void __launch_bounds__(256, 1) k_attn(int m) {
    extern __shared__ char smraw[];
    uint32_t sb0;
    asm("{\n.reg .u64 t;\ncvta.to.shared.u64 t, %1;\ncvt.u32.u64 %0, t;\n}" : "=r"(sb0) : "l"(smraw));
    uint32_t sb = (sb0 + 1023u) & ~1023u;

    int tid = threadIdx.x, wid = tid >> 5, lane = tid & 31;
    int lr = lane & 7, lg = lane >> 3;
    int hbit = lg >> 1;
    int rbit = lg & 1;
    int bid = blockIdx.x;
    int H = (int)gridDim.x - 128;

    // lane-constant address components (c-independent)
    int row_a = 16 * wid + rbit * 8 + lr;
    uint32_t aR = (uint32_t)(((row_a >> 3) * 1024) + ((row_a & 7) * 128));
    uint32_t ax = (uint32_t)(row_a & 7);
    int r0 = rbit * 8 + lr;
    uint32_t bR = (uint32_t)(((r0 >> 3) * 1024) + ((r0 & 7) * 128));
    uint32_t bx = (uint32_t)(r0 & 7);
    uint32_t lOff = (uint32_t)((hbit * 8 + lr) * 48 + rbit * 16);
    uint32_t cB[8];
#pragma unroll
    for (int s = 0; s < 8; s++) {
        int ch = 2 * s + hbit;
        cB[s] = (uint32_t)(((ch >> 3) * 16384) + ((((uint32_t)(ch & 7) ^ bx) << 4)));
    }
    int rW = 16 * wid + (lane >> 2);
    uint32_t wIn = (uint32_t)(4 * (lane & 3));
    int qbase = ((lane >> 4) << 3) + (lane & 7);
    int chW = 2 * wid + ((lane >> 3) & 1);
    const float C = 2.8853900817779268f;   // 2/ln2

    int A1 = 65 - m, A2 = 64 - m, tail = TTOT - 128 * m;
    int t = 0, tend = 0;
    if (bid >= 128) {
        int q = (tail + H - 1) / H;
        t = (bid - 128) * q;
        tend = min(tail, t + q);
        if (t >= tend) return;
    }

    for (;;) {   // segment loop
        int c, d0, len;
        if (bid < 128) {
            c = bid; d0 = 0;
            len = (H > 0) ? m : ((c < 64) ? 65 : 64);
        } else {
            int b1 = 64 * A1;
            if (t < b1) { c = t / A1; int o = t - c * A1; d0 = m + o; len = A1 - o; }
            else { int u = t - b1; int cc = u / A2; c = 64 + cc; int o = u - cc * A2; d0 = m + o; len = A2 - o; }
            if (len > tend - t) len = tend - t;
        }

        // segment prologue: G0={Q,LC}, G1={K(d0),L(d0)}, G2={K(d0+1),L(d0+1)}
        load_ftile(sb + S_Q, c * 128, tid);
        load_ltile(sb + S_LC, c * 128, tid);
        CPC();
        load_ftile(sb + S_K(0), ((c + d0) & 127) * 128, tid);
        load_ltile(sb + S_L(0), ((c + d0) & 127) * 128, tid);
        CPC();
        if (len > 1) {
            load_ftile(sb + S_K(1), ((c + d0 + 1) & 127) * 128, tid);
            load_ltile(sb + S_L(1), ((c + d0 + 1) & 127) * 128, tid);
            CPC();
            CPW(2);
        } else {
            CPW(1);
        }
        __syncthreads();

        uint32_t A[8][4];
#pragma unroll
        for (int s = 0; s < 8; s++) {
            int ch = 2 * s + hbit;
            uint32_t cA = (uint32_t)(((ch >> 3) * 16384) + ((((uint32_t)(ch & 7) ^ ax) << 4)));
            ldsm4(A[s], sb + S_Q + aR + cA);
        }
        uint32_t LC[8][4];
#pragma unroll
        for (int s = 0; s < 8; s++) ldsm4t(LC[s], sb + S_LC + lOff + (uint32_t)(s * 768));

        float O0[4] = {0.f, 0.f, 0.f, 0.f};
        float O1[4] = {0.f, 0.f, 0.f, 0.f};

        for (int i = 0; i < len; i++) {
            int d = d0 + i;
            int kb = i % 3, wb = i & 1;
            int j = (c + d) & 127;
            if (i + 2 < len) {
                int jn = (c + d + 2) & 127;
                load_ftile(sb + S_K((i + 2) % 3), jn * 128, tid);
                load_ltile(sb + S_L((i + 2) % 3), jn * 128, tid);
                CPC();
                CPW(2);
            } else if (i + 1 < len) {
                CPW(1);
            } else {
                CPW(0);
            }
            uint32_t KH = sb + S_K(kb) + bR;
            uint32_t Lb = sb + (uint32_t)S_L(kb) + lOff;
            uint32_t WB = sb + (uint32_t)S_W(wb);

#pragma unroll
            for (int p = 0; p < 8; p++) {
                float S0[4] = {0.f, 0.f, 0.f, 0.f};
                float S1[4] = {0.f, 0.f, 0.f, 0.f};
                uint32_t kbad = KH + (uint32_t)(p * 2048);
#pragma unroll
                for (int s = 0; s < 8; s++) {
                    uint32_t bb[4];
                    ldsm4(bb, kbad + cB[s]);
                    mmaf16(S0, A[s], bb[0], bb[2]);
                    mmaf16(S1, A[s], bb[1], bb[3]);
                }
                uint32_t W[4];
                W[0] = packh(ex2a(S0[0] * C), ex2a(S0[1] * C));
                W[1] = packh(ex2a(S0[2] * C), ex2a(S0[3] * C));
                W[2] = packh(ex2a(S1[0] * C), ex2a(S1[1] * C));
                W[3] = packh(ex2a(S1[2] * C), ex2a(S1[3] * C));
                uint32_t bf[4];
                ldsm4t(bf, Lb + (uint32_t)(p * 768));
                mmaf16(O0, W, bf[0], bf[2]);
                mmaf16(O1, W, bf[1], bf[3]);
                sts32(WB + swoff(rW, 2 * p) + wIn,         W[0]);
                sts32(WB + swoff(rW + 8, 2 * p) + wIn,     W[1]);
                sts32(WB + swoff(rW, 2 * p + 1) + wIn,     W[2]);
                sts32(WB + swoff(rW + 8, 2 * p + 1) + wIn, W[3]);
            }

            __syncthreads();   // W(d) complete; ring(d) reads done

            if (d > 0) {
                float F0[4] = {0.f, 0.f, 0.f, 0.f};
                float F1[4] = {0.f, 0.f, 0.f, 0.f};
#pragma unroll
                for (int s = 0; s < 8; s++) {
                    uint32_t At[4];
                    ldsm4t(At, WB + swoff(16 * s + qbase, chW));
                    mmaf16(F0, At, LC[s][0], LC[s][2]);
                    mmaf16(F1, At, LC[s][1], LC[s][3]);
                }
                int krow = 16 * wid + (lane >> 2);
                int cp = 2 * (lane & 3);
                float* pb = g_acc + ((size_t)j * 128 + krow) * 12;
                red2(pb + cp,      F0[0], F0[1]);
                red2(pb + 96 + cp, F0[2], F0[3]);
                if ((lane & 3) < 2) {
                    red2(pb + 8 + cp,      F1[0], F1[1]);
                    red2(pb + 96 + 8 + cp, F1[2], F1[3]);
                }
            }
        }

        // flush local partial into row-block c
        {
            int qrow = 16 * wid + (lane >> 2);
            int cp = 2 * (lane & 3);
            float* pb = g_acc + ((size_t)c * 128 + qrow) * 12;
            red2(pb + cp,      O0[0], O0[1]);
            red2(pb + 96 + cp, O0[2], O0[3]);
            if ((lane & 3) < 2) {
                red2(pb + 8 + cp,      O1[0], O1[1]);
                red2(pb + 96 + 8 + cp, O1[2], O1[3]);
            }
        }

        if (bid < 128) break;
        t += len;
        if (t >= tend) break;
    }
}

// ---------------- reduction: divide + class-scale (768 KB read) ----------------
__global__ void __launch_bounds__(128) k_red(float* __restrict__ out) {
    __shared__ float sInv[NC];
    int j = blockIdx.x, tid = threadIdx.x;
    if (tid == 0) {
        float tot = 0.f;
#pragma unroll
        for (int q = 0; q < NC; q++) tot += g_cnt[q];
#pragma unroll
        for (int q = 0; q < NC; q++) {
            float dd = g_cnt[q];
            sInv[q] = 1.f / ((dd == 0.f) ? tot : dd);
        }
    }
    __syncthreads();
    const float* ar = g_acc + ((size_t)j * 128 + tid) * 12;
    float4 a = *(const float4*)ar;
    float4 b = *(const float4*)(ar + 4);
    float4 cq = *(const float4*)(ar + 8);
    float dv = 1.f / cq.z;                 // col 10 = denominator
    float* op = out + ((size_t)j * 128 + tid) * NC;
    op[0] = a.x * dv * sInv[0]; op[1] = a.y * dv * sInv[1];
    op[2] = a.z * dv * sInv[2]; op[3] = a.w * dv * sInv[3];
    op[4] = b.x * dv * sInv[4]; op[5] = b.y * dv * sInv[5];
    op[6] = b.z * dv * sInv[6]; op[7] = b.w * dv * sInv[7];
    op[8] = cq.x * dv * sInv[8]; op[9] = cq.y * dv * sInv[9];
}

// ---------------- launcher ----------------
extern "C" void kernel_launch(void* const* d_in, const int* in_sizes, int n_in,
                              void* d_out, int out_size) {
    const float* anchor   = (const float*)d_in[0];
    const float* positive = (const float*)d_in[1];
    const float* lb_feat  = (const float*)d_in[2];
    const float* lb_oh    = (const float*)d_in[3];
    const float* logits1  = (const float*)d_in[4];
    const float* logits2  = (const float*)d_in[5];
    float* out = (float*)d_out;

    int dev = 0, sm = 148;
    cudaGetDevice(&dev);
    cudaDeviceGetAttribute(&sm, cudaDevAttrMultiProcessorCount, dev);
    int H = (sm > 128) ? (sm - 128) : 0;
    if (H > 64) H = 64;
    int m = (H > 0) ? (TTOT + (128 + H) - 1) / (128 + H) : 65;
    if (H > 0 && m > 64) m = 64;

    cudaFuncSetAttribute(k_attn, cudaFuncAttributeMaxDynamicSharedMemorySize, SMEM_REQ);

    k_norm<<<(NTOT * 32) / 256, 256>>>(lb_feat, anchor, positive);
    k_prep<<<40, 256>>>(lb_oh, logits1, logits2);
    k_attn<<<128 + H, 256, SMEM_REQ>>>(m);
    k_red<<<128, 128>>>(out);
}

// round 16
// speedup vs baseline: 1.5106x; 1.1090x over previous
#include <cuda_runtime.h>
#include <cuda_fp16.h>
#include <cstdint>

#define NTOT 16384
#define BLB  4096
#define BULB 6144
#define DIM  128
#define NC   10
#define LSTB 24
#define TTOT 8256   // 64*65 + 64*64 symmetric tiles

// ---------------- device scratch ----------------
__device__ __align__(256) __half g_F[NTOT * DIM];
__device__ __align__(256) __half g_Lh[NTOT * LSTB];     // 10 probs, [10]=1, rest 0
__device__ __align__(256) float g_acc[128 * 128 * 12];  // 768 KB accumulator (L2-resident)
__device__ float g_cnt[NC];

// ---------------- helpers ----------------
__device__ __forceinline__ float ex2a(float x) {
    float y; asm("ex2.approx.ftz.f32 %0,%1;" : "=f"(y) : "f"(x)); return y;
}
__device__ __forceinline__ void cpa16(uint32_t dst, const void* src) {
    asm volatile("cp.async.cg.shared.global [%0], [%1], 16;" :: "r"(dst), "l"(src));
}
#define CPC()  asm volatile("cp.async.commit_group;" ::: "memory")
#define CPW(n) asm volatile("cp.async.wait_group %0;" :: "n"(n) : "memory")

__device__ __forceinline__ void ldsm4(uint32_t* r, uint32_t a) {
    asm volatile("ldmatrix.sync.aligned.m8n8.x4.shared.b16 {%0,%1,%2,%3},[%4];"
        : "=r"(r[0]), "=r"(r[1]), "=r"(r[2]), "=r"(r[3]) : "r"(a));
}
__device__ __forceinline__ void ldsm4t(uint32_t* r, uint32_t a) {
    asm volatile("ldmatrix.sync.aligned.m8n8.x4.trans.shared.b16 {%0,%1,%2,%3},[%4];"
        : "=r"(r[0]), "=r"(r[1]), "=r"(r[2]), "=r"(r[3]) : "r"(a));
}
__device__ __forceinline__ void mmaf16(float* d, const uint32_t* a, uint32_t b0, uint32_t b1) {
    asm volatile("mma.sync.aligned.m16n8k16.row.col.f32.f16.f16.f32 "
        "{%0,%1,%2,%3},{%4,%5,%6,%7},{%8,%9},{%0,%1,%2,%3};"
        : "+f"(d[0]), "+f"(d[1]), "+f"(d[2]), "+f"(d[3])
        : "r"(a[0]), "r"(a[1]), "r"(a[2]), "r"(a[3]), "r"(b0), "r"(b1));
}
__device__ __forceinline__ uint32_t packh(float lo, float hi) {
    uint32_t r; asm("cvt.rn.f16x2.f32 %0, %1, %2;" : "=r"(r) : "f"(hi), "f"(lo)); return r;
}
__device__ __forceinline__ void sts32(uint32_t a, uint32_t v) {
    asm volatile("st.shared.b32 [%0],%1;" :: "r"(a), "r"(v) : "memory");
}
__device__ __forceinline__ void red2(float* p, float x, float y) {
    atomicAdd(reinterpret_cast<float2*>(p), make_float2(x, y));   // RED.E.ADD.F32x2
}

// ---------------- smem layout (byte offsets from 1024-aligned base) ----------------
#define S_Q     0
#define S_K(b)  (32768 + (b) * 32768)      // 3 buffers
#define S_W(b)  (131072 + (b) * 32768)     // 2 buffers
#define S_L(b)  (196608 + (b) * 6144)      // 3 buffers
#define S_LC    215040                     // L_c copy for trans PV
#define SMEM_REQ (221184 + 1024)

// SW128 blocked layout for a 128x128 fp16 tile (row 0..127, 16B-chunk 0..15)
__device__ __forceinline__ uint32_t swoff(int row, int ch) {
    return (uint32_t)(((row >> 3) * 1024) + ((ch >> 3) * 16384)
                      + ((row & 7) * 128) + ((((ch & 7) ^ (row & 7)) << 4)));
}

__device__ __forceinline__ void load_ftile(uint32_t dst, int rowbase, int tid) {
#pragma unroll
    for (int i = 0; i < 8; i++) {
        int idx = i * 256 + tid;
        int row = idx >> 4, ch = idx & 15;
        cpa16(dst + swoff(row, ch), g_F + (size_t)(rowbase + row) * DIM + ch * 8);
    }
}
__device__ __forceinline__ void load_ltile(uint32_t dst, int rowbase, int tid) {
#pragma unroll
    for (int i = 0; i < 2; i++) {
        int idx = i * 256 + tid;
        if (idx < 384) {
            int row = idx / 3, part = idx - row * 3;
            cpa16(dst + (uint32_t)(row * 48 + part * 16),
                  g_Lh + (size_t)(rowbase + row) * LSTB + part * 8);
        }
    }
}

// ---------------- prep: normalize + zero counters/accumulator ----------------
__global__ void k_norm(const float* __restrict__ lb, const float* __restrict__ an,
                       const float* __restrict__ po) {
    int gt = blockIdx.x * blockDim.x + threadIdx.x;
    if (gt < NC) g_cnt[gt] = 0.f;
    if (gt < 128 * 128 * 12) g_acc[gt] = 0.f;
    int w = gt >> 5;
    int ln = threadIdx.x & 31;
    if (w >= NTOT) return;
    const float* s = (w < BLB) ? lb + (size_t)w * DIM
                   : (w < BLB + BULB) ? an + (size_t)(w - BLB) * DIM
                                      : po + (size_t)(w - BLB - BULB) * DIM;
    float4 v = ((const float4*)s)[ln];
    float q = v.x*v.x + v.y*v.y + v.z*v.z + v.w*v.w;
#pragma unroll
    for (int o = 16; o; o >>= 1) q += __shfl_xor_sync(0xffffffffu, q, o);
    float iv = 1.f / fmaxf(sqrtf(q), 1e-12f);
    __half2 h0 = __floats2half2_rn(v.x * iv, v.y * iv);
    __half2 h1 = __floats2half2_rn(v.z * iv, v.w * iv);
    size_t base = (size_t)w * DIM + ln * 4;
    *(__half2*)(g_F + base)     = h0;
    *(__half2*)(g_F + base + 2) = h1;
}

// ---------------- prep: labeled + unlabeled logits (fused) ----------------
__global__ void __launch_bounds__(256) k_prep(const float* __restrict__ oh,
                                              const float* __restrict__ l1,
                                              const float* __restrict__ l2) {
    int bid = blockIdx.x, tid = threadIdx.x;
    if (bid < 16) {
        int r = bid * 256 + tid;
#pragma unroll
        for (int c = 0; c < NC; c++) {
            float v = oh[r * NC + c];
            g_Lh[r * LSTB + c] = __float2half(v);
            if (v != 0.f) atomicAdd(&g_cnt[c], v);
        }
        g_Lh[r * LSTB + 10] = __float2half(1.0f);
#pragma unroll
        for (int c = 11; c < LSTB; c++) g_Lh[r * LSTB + c] = __float2half(0.0f);
        return;
    }
    int r = (bid - 16) * 256 + tid;
    float a[NC], b[NC];
#pragma unroll
    for (int i = 0; i < NC; i++) { a[i] = l1[r*NC+i]; b[i] = l2[r*NC+i]; }
    float m1 = -1e30f, m2 = -1e30f;
#pragma unroll
    for (int i = 0; i < NC; i++) { m1 = fmaxf(m1, a[i]); m2 = fmaxf(m2, b[i]); }
    float s1 = 0.f, s2 = 0.f;
#pragma unroll
    for (int i = 0; i < NC; i++) { s1 += expf(2.f*(a[i]-m1)); s2 += expf(2.f*(b[i]-m2)); }
    bool take1 = (s1 <= s2);
    float lg[NC];
#pragma unroll
    for (int i = 0; i < NC; i++) lg[i] = take1 ? a[i] : b[i];

    float m = -1e30f;
#pragma unroll
    for (int i = 0; i < NC; i++) m = fmaxf(m, lg[i]);
    float e[NC], s = 0.f;
#pragma unroll
    for (int i = 0; i < NC; i++) { e[i] = expf(lg[i]-m); s += e[i]; }
#pragma unroll
    for (int i = 0; i < NC; i++) if (e[i] < 0.95f * s) lg[i] = 0.f;

    float mx = lg[0]; int idx = 0;
#pragma unroll
    for (int i = 1; i < NC; i++) if (lg[i] > mx) { mx = lg[i]; idx = i; }
    if (mx != 0.f) atomicAdd(&g_cnt[idx], 2.f);

    float mm = -1e30f;
#pragma unroll
    for (int i = 0; i < NC; i++) mm = fmaxf(mm, lg[i]);
    float p[NC], ss = 0.f;
#pragma unroll
    for (int i = 0; i < NC; i++) { p[i] = expf(2.f*(lg[i]-mm)); ss += p[i]; }
    float inv = 1.f / ss;
    int r1 = BLB + r, r2 = BLB + BULB + r;
#pragma unroll
    for (int c = 0; c < NC; c++) {
        __half v = __float2half(p[c] * inv);
        g_Lh[r1*LSTB + c] = v; g_Lh[r2*LSTB + c] = v;
    }
    g_Lh[r1*LSTB + 10] = __float2half(1.0f);
    g_Lh[r2*LSTB + 10] = __float2half(1.0f);
#pragma unroll
    for (int c = 11; c < LSTB; c++) {
        g_Lh[r1*LSTB + c] = __float2half(0.0f);
        g_Lh[r2*LSTB + c] = __float2half(0.0f);
    }
}

// ---------------- main attention: symmetric tiles, 32q x 64k per warp ----------------
// Main CTA c: tiles (c, c+d) d=0..m-1. Helper CTAs split the c-major tail list.
// Warp wid: rband = wid&3 (32 q-rows, 2 bands of 16), ph = wid>>2 (64 k-cols).
// All partial outputs merge into g_acc via float2 atomicAdd.
__global__ void __launch_bounds__(256, 1) k_attn(int m) {
    extern __shared__ char smraw[];
    uint32_t sb0;
    asm("{\n.reg .u64 t;\ncvta.to.shared.u64 t, %1;\ncvt.u32.u64 %0, t;\n}" : "=r"(sb0) : "l"(smraw));
    uint32_t sb = (sb0 + 1023u) & ~1023u;

    int tid = threadIdx.x, wid = tid >> 5, lane = tid & 31;
    int rband = wid & 3, ph = wid >> 2;
    int lr = lane & 7, lg = lane >> 3;
    int hbit = lg >> 1;
    int rbit = lg & 1;
    int bid = blockIdx.x;
    int H = (int)gridDim.x - 128;

    // A-frag row components per band: row_a = 32*rband + 16*band + rbit*8 + lr
    uint32_t aR[2];
#pragma unroll
    for (int band = 0; band < 2; band++)
        aR[band] = (uint32_t)((4 * rband + 2 * band + rbit) * 1024 + lr * 128);
    // cA[s]: ch = 2s + hbit, column xor with (row_a & 7) = lr
    uint32_t cA[8];
#pragma unroll
    for (int s = 0; s < 8; s++) {
        int ch = 2 * s + hbit;
        cA[s] = (uint32_t)(((ch >> 3) * 16384) + ((((uint32_t)(ch & 7) ^ (uint32_t)lr) << 4)));
    }
    // B components (lane-only, same as validated): r0 = rbit*8 + lr
    int r0 = rbit * 8 + lr;
    uint32_t bR = (uint32_t)(((r0 >> 3) * 1024) + ((r0 & 7) * 128));
    uint32_t bx = (uint32_t)(r0 & 7);
    uint32_t cB[8];
#pragma unroll
    for (int s = 0; s < 8; s++) {
        int ch = 2 * s + hbit;
        cB[s] = (uint32_t)(((ch >> 3) * 16384) + ((((uint32_t)(ch & 7) ^ bx) << 4)));
    }
    uint32_t lOff = (uint32_t)((hbit * 8 + lr) * 48 + rbit * 16);
    // W-store rows per band
    int rW[2] = { 32 * rband + (lane >> 2), 32 * rband + 16 + (lane >> 2) };
    uint32_t wIn = (uint32_t)(4 * (lane & 3));
    // trans-PV (wid-linear, unchanged)
    int qbase = ((lane >> 4) << 3) + (lane & 7);
    int chW = 2 * wid + ((lane >> 3) & 1);
    const float C = 2.8853900817779268f;   // 2/ln2

    int A1 = 65 - m, A2 = 64 - m, tail = TTOT - 128 * m;
    int t = 0, tend = 0;
    if (bid >= 128) {
        int q = (tail + H - 1) / H;
        t = (bid - 128) * q;
        tend = min(tail, t + q);
        if (t >= tend) return;
    }

    for (;;) {   // segment loop
        int c, d0, len;
        if (bid < 128) {
            c = bid; d0 = 0;
            len = (H > 0) ? m : ((c < 64) ? 65 : 64);
        } else {
            int b1 = 64 * A1;
            if (t < b1) { c = t / A1; int o = t - c * A1; d0 = m + o; len = A1 - o; }
            else { int u = t - b1; int cc = u / A2; c = 64 + cc; int o = u - cc * A2; d0 = m + o; len = A2 - o; }
            if (len > tend - t) len = tend - t;
        }

        // segment prologue: G0={Q,LC}, G1={K(d0),L(d0)}, G2={K(d0+1),L(d0+1)}
        load_ftile(sb + S_Q, c * 128, tid);
        load_ltile(sb + S_LC, c * 128, tid);
        CPC();
        load_ftile(sb + S_K(0), ((c + d0) & 127) * 128, tid);
        load_ltile(sb + S_L(0), ((c + d0) & 127) * 128, tid);
        CPC();
        if (len > 1) {
            load_ftile(sb + S_K(1), ((c + d0 + 1) & 127) * 128, tid);
            load_ltile(sb + S_L(1), ((c + d0 + 1) & 127) * 128, tid);
            CPC();
            CPW(2);
        } else {
            CPW(1);
        }
        __syncthreads();

        // hoist A fragments for both bands
        uint32_t A[2][8][4];
#pragma unroll
        for (int band = 0; band < 2; band++)
#pragma unroll
            for (int s = 0; s < 8; s++)
                ldsm4(A[band][s], sb + S_Q + aR[band] + cA[s]);
        uint32_t LC[8][4];
#pragma unroll
        for (int s = 0; s < 8; s++) ldsm4t(LC[s], sb + S_LC + lOff + (uint32_t)(s * 768));

        float O[2][2][4];
#pragma unroll
        for (int band = 0; band < 2; band++)
#pragma unroll
            for (int h = 0; h < 2; h++)
#pragma unroll
                for (int e = 0; e < 4; e++) O[band][h][e] = 0.f;

        for (int i = 0; i < len; i++) {
            int d = d0 + i;
            int kb = i % 3, wb = i & 1;
            int j = (c + d) & 127;
            if (i + 2 < len) {
                int jn = (c + d + 2) & 127;
                load_ftile(sb + S_K((i + 2) % 3), jn * 128, tid);
                load_ltile(sb + S_L((i + 2) % 3), jn * 128, tid);
                CPC();
                CPW(2);
            } else if (i + 1 < len) {
                CPW(1);
            } else {
                CPW(0);
            }
            uint32_t KH = sb + S_K(kb) + bR;
            uint32_t Lb = sb + (uint32_t)S_L(kb) + lOff;
            uint32_t WB = sb + (uint32_t)S_W(wb);

            // QK + exp + local PV + W store for this warp's 4 n-tiles (cols 64*ph..)
#pragma unroll
            for (int pp = 0; pp < 4; pp++) {
                int p = 4 * ph + pp;
                float S[2][2][4];
#pragma unroll
                for (int band = 0; band < 2; band++)
#pragma unroll
                    for (int h = 0; h < 2; h++)
#pragma unroll
                        for (int e = 0; e < 4; e++) S[band][h][e] = 0.f;
                uint32_t kbad = KH + (uint32_t)(p * 2048);
#pragma unroll
                for (int s = 0; s < 8; s++) {
                    uint32_t bb[4];
                    ldsm4(bb, kbad + cB[s]);
#pragma unroll
                    for (int band = 0; band < 2; band++) {
                        mmaf16(S[band][0], A[band][s], bb[0], bb[2]);
                        mmaf16(S[band][1], A[band][s], bb[1], bb[3]);
                    }
                }
                uint32_t bf[4];
                ldsm4t(bf, Lb + (uint32_t)(p * 768));
#pragma unroll
                for (int band = 0; band < 2; band++) {
                    uint32_t W[4];
                    W[0] = packh(ex2a(S[band][0][0] * C), ex2a(S[band][0][1] * C));
                    W[1] = packh(ex2a(S[band][0][2] * C), ex2a(S[band][0][3] * C));
                    W[2] = packh(ex2a(S[band][1][0] * C), ex2a(S[band][1][1] * C));
                    W[3] = packh(ex2a(S[band][1][2] * C), ex2a(S[band][1][3] * C));
                    mmaf16(O[band][0], W, bf[0], bf[2]);
                    mmaf16(O[band][1], W, bf[1], bf[3]);
                    sts32(WB + swoff(rW[band], 2 * p) + wIn,         W[0]);
                    sts32(WB + swoff(rW[band] + 8, 2 * p) + wIn,     W[1]);
                    sts32(WB + swoff(rW[band], 2 * p + 1) + wIn,     W[2]);
                    sts32(WB + swoff(rW[band] + 8, 2 * p + 1) + wIn, W[3]);
                }
            }

            __syncthreads();   // W(d) complete; ring(d) reads done

            if (d > 0) {
                float F0[4] = {0.f, 0.f, 0.f, 0.f};
                float F1[4] = {0.f, 0.f, 0.f, 0.f};
#pragma unroll
                for (int s = 0; s < 8; s++) {
                    uint32_t At[4];
                    ldsm4t(At, WB + swoff(16 * s + qbase, chW));
                    mmaf16(F0, At, LC[s][0], LC[s][2]);
                    mmaf16(F1, At, LC[s][1], LC[s][3]);
                }
                int krow = 16 * wid + (lane >> 2);
                int cp = 2 * (lane & 3);
                float* pb = g_acc + ((size_t)j * 128 + krow) * 12;
                red2(pb + cp,      F0[0], F0[1]);
                red2(pb + 96 + cp, F0[2], F0[3]);
                if ((lane & 3) < 2) {
                    red2(pb + 8 + cp,      F1[0], F1[1]);
                    red2(pb + 96 + 8 + cp, F1[2], F1[3]);
                }
            }
        }

        // flush local partials (both bands) into row-block c
        {
            int cp = 2 * (lane & 3);
#pragma unroll
            for (int band = 0; band < 2; band++) {
                int qrow = 32 * rband + 16 * band + (lane >> 2);
                float* pb = g_acc + ((size_t)c * 128 + qrow) * 12;
                red2(pb + cp,      O[band][0][0], O[band][0][1]);
                red2(pb + 96 + cp, O[band][0][2], O[band][0][3]);
                if ((lane & 3) < 2) {
                    red2(pb + 8 + cp,      O[band][1][0], O[band][1][1]);
                    red2(pb + 96 + 8 + cp, O[band][1][2], O[band][1][3]);
                }
            }
        }

        if (bid < 128) break;
        t += len;
        if (t >= tend) break;
    }
}

// ---------------- reduction: divide + class-scale (768 KB read) ----------------
__global__ void __launch_bounds__(128) k_red(float* __restrict__ out) {
    __shared__ float sInv[NC];
    int j = blockIdx.x, tid = threadIdx.x;
    if (tid == 0) {
        float tot = 0.f;
#pragma unroll
        for (int q = 0; q < NC; q++) tot += g_cnt[q];
#pragma unroll
        for (int q = 0; q < NC; q++) {
            float dd = g_cnt[q];
            sInv[q] = 1.f / ((dd == 0.f) ? tot : dd);
        }
    }
    __syncthreads();
    const float* ar = g_acc + ((size_t)j * 128 + tid) * 12;
    float4 a = *(const float4*)ar;
    float4 b = *(const float4*)(ar + 4);
    float4 cq = *(const float4*)(ar + 8);
    float dv = 1.f / cq.z;                 // col 10 = denominator
    float* op = out + ((size_t)j * 128 + tid) * NC;
    op[0] = a.x * dv * sInv[0]; op[1] = a.y * dv * sInv[1];
    op[2] = a.z * dv * sInv[2]; op[3] = a.w * dv * sInv[3];
    op[4] = b.x * dv * sInv[4]; op[5] = b.y * dv * sInv[5];
    op[6] = b.z * dv * sInv[6]; op[7] = b.w * dv * sInv[7];
    op[8] = cq.x * dv * sInv[8]; op[9] = cq.y * dv * sInv[9];
}

// ---------------- launcher ----------------
extern "C" void kernel_launch(void* const* d_in, const int* in_sizes, int n_in,
                              void* d_out, int out_size) {
    const float* anchor   = (const float*)d_in[0];
    const float* positive = (const float*)d_in[1];
    const float* lb_feat  = (const float*)d_in[2];
    const float* lb_oh    = (const float*)d_in[3];
    const float* logits1  = (const float*)d_in[4];
    const float* logits2  = (const float*)d_in[5];
    float* out = (float*)d_out;

    int dev = 0, sm = 148;
    cudaGetDevice(&dev);
    cudaDeviceGetAttribute(&sm, cudaDevAttrMultiProcessorCount, dev);
    int H = (sm > 128) ? (sm - 128) : 0;
    if (H > 64) H = 64;
    int m = (H > 0) ? (TTOT + (128 + H) - 1) / (128 + H) : 65;
    if (H > 0 && m > 64) m = 64;

    cudaFuncSetAttribute(k_attn, cudaFuncAttributeMaxDynamicSharedMemorySize, SMEM_REQ);

    k_norm<<<(NTOT * 32) / 256, 256>>>(lb_feat, anchor, positive);
    k_prep<<<40, 256>>>(lb_oh, logits1, logits2);
    k_attn<<<128 + H, 256, SMEM_REQ>>>(m);
    k_red<<<128, 128>>>(out);
}